// round 1
// baseline (speedup 1.0000x reference)
#include <cuda_runtime.h>
#include <math.h>

#define Bb 2
#define Ss 2048
#define Dd 1024
#define Hh 16
#define HD 64
#define Mm (Bb*Ss)      /* 4096 */
#define N3 (3*Dd)       /* 3072 */

// Scratch: q,k,v,attn_out in [B,H,S,hd] layout. 16MB each.
__device__ float g_q [Bb*Hh*Ss*HD];
__device__ float g_k [Bb*Hh*Ss*HD];
__device__ float g_v [Bb*Hh*Ss*HD];
__device__ float g_ao[Bb*Hh*Ss*HD];

// ---------------------------------------------------------------------------
// Kernel 1: QKV GEMM.  C[M,3D] = X[M,D] @ W[D,3D] + b, scattered to q/k/v
// in [B,H,S,hd] layout.  64x64 tile, BK=16, 256 threads, 4x4 per thread.
// ---------------------------------------------------------------------------
__global__ void __launch_bounds__(256) qkv_gemm(const float* __restrict__ X,
                                                const float* __restrict__ W,
                                                const float* __restrict__ bias)
{
    __shared__ float As[16][68];   // [k][m] transposed, padded
    __shared__ float Bs[16][64];   // [k][n]

    const int bm = blockIdx.y * 64;
    const int bn = blockIdx.x * 64;
    const int tid = threadIdx.x;
    const int ty = tid >> 4, tx = tid & 15;
    const int arow = tid >> 2, ac = (tid & 3) * 4;   // A loader: 64 rows x 16 cols
    const int brow = tid >> 4, bc = (tid & 15) * 4;  // B loader: 16 rows x 64 cols

    float acc[4][4] = {};

    for (int k0 = 0; k0 < Dd; k0 += 16) {
        float4 a = *(const float4*)(X + (size_t)(bm + arow) * Dd + k0 + ac);
        As[ac + 0][arow] = a.x;
        As[ac + 1][arow] = a.y;
        As[ac + 2][arow] = a.z;
        As[ac + 3][arow] = a.w;
        *(float4*)&Bs[brow][bc] =
            *(const float4*)(W + (size_t)(k0 + brow) * N3 + bn + bc);
        __syncthreads();
#pragma unroll
        for (int kk = 0; kk < 16; kk++) {
            float4 av = *(const float4*)&As[kk][ty * 4];
            float4 bv = *(const float4*)&Bs[kk][tx * 4];
            acc[0][0] += av.x * bv.x; acc[0][1] += av.x * bv.y;
            acc[0][2] += av.x * bv.z; acc[0][3] += av.x * bv.w;
            acc[1][0] += av.y * bv.x; acc[1][1] += av.y * bv.y;
            acc[1][2] += av.y * bv.z; acc[1][3] += av.y * bv.w;
            acc[2][0] += av.z * bv.x; acc[2][1] += av.z * bv.y;
            acc[2][2] += av.z * bv.z; acc[2][3] += av.z * bv.w;
            acc[3][0] += av.w * bv.x; acc[3][1] += av.w * bv.y;
            acc[3][2] += av.w * bv.z; acc[3][3] += av.w * bv.w;
        }
        __syncthreads();
    }

    // Epilogue: bias + scatter into q/k/v head layout.
    // Within this 64-wide N tile, "which" tensor and head h are uniform.
    const int which = bn / Dd;              // 0=q 1=k 2=v
    const int h = (bn % Dd) / HD;
    float* dst = (which == 0) ? g_q : ((which == 1) ? g_k : g_v);
#pragma unroll
    for (int i = 0; i < 4; i++) {
        const int m = bm + ty * 4 + i;
        const int b = m / Ss, s = m % Ss;
        float* drow = dst + ((size_t)(b * Hh + h) * Ss + s) * HD;
#pragma unroll
        for (int j = 0; j < 4; j++) {
            const int n = bn + tx * 4 + j;
            drow[tx * 4 + j] = acc[i][j] + bias[n];
        }
    }
}

// ---------------------------------------------------------------------------
// Kernel 2: causal flash attention, fp32.
// Grid (S/128, B*H), 128 threads.  1 thread = 1 query row.
// q-row and o-row live in registers; K/V tiles of 32 keys in smem.
// Fully-masked key tiles are skipped (causal halves the work).
// ---------------------------------------------------------------------------
__global__ void __launch_bounds__(128) attn_kernel()
{
    __shared__ float Ks[32 * 64];
    __shared__ float Vs[32 * 64];

    const int bh = blockIdx.y;
    const int q0 = blockIdx.x * 128;
    const int tid = threadIdx.x;
    const int qi = q0 + tid;

    const float* qrow = g_q + ((size_t)bh * Ss + qi) * HD;
    float q[64], o[64];
#pragma unroll
    for (int d = 0; d < 64; d++) { q[d] = qrow[d] * 0.125f; o[d] = 0.f; }

    float mrun = -1e30f, lrun = 0.f;
    const int ntiles = (q0 + 128) / 32;   // only tiles that intersect causal region

    for (int kt = 0; kt < ntiles; kt++) {
        const int k0 = kt * 32;
        const float4* Kg = (const float4*)(g_k + ((size_t)bh * Ss + k0) * HD);
        const float4* Vg = (const float4*)(g_v + ((size_t)bh * Ss + k0) * HD);
        __syncthreads();
#pragma unroll
        for (int i = 0; i < 4; i++) {
            const int idx = tid + i * 128;          // 512 float4 per tile
            ((float4*)Ks)[idx] = Kg[idx];
            ((float4*)Vs)[idx] = Vg[idx];
        }
        __syncthreads();

        if (k0 <= qi) {   // row participates in this tile
            float p[32];
            float tmax = mrun;
#pragma unroll
            for (int j = 0; j < 32; j++) {
                const float4* kr = (const float4*)&Ks[j * 64];
                float s0 = 0.f, s1 = 0.f, s2 = 0.f, s3 = 0.f;
#pragma unroll
                for (int d4 = 0; d4 < 16; d4++) {
                    float4 kv = kr[d4];            // uniform addr -> broadcast
                    s0 += q[d4 * 4 + 0] * kv.x;
                    s1 += q[d4 * 4 + 1] * kv.y;
                    s2 += q[d4 * 4 + 2] * kv.z;
                    s3 += q[d4 * 4 + 3] * kv.w;
                }
                float s = (s0 + s1) + (s2 + s3);
                if (k0 + j > qi) s = -1e30f;       // causal mask
                p[j] = s;
                tmax = fmaxf(tmax, s);
            }
            const float corr = __expf(mrun - tmax);
            lrun *= corr;
#pragma unroll
            for (int d = 0; d < 64; d++) o[d] *= corr;
            float lsum = 0.f;
#pragma unroll
            for (int j = 0; j < 32; j++) {
                const float pj = __expf(p[j] - tmax);
                p[j] = pj;
                lsum += pj;
            }
            lrun += lsum;
#pragma unroll
            for (int j = 0; j < 32; j++) {
                const float pj = p[j];
                const float4* vr = (const float4*)&Vs[j * 64];
#pragma unroll
                for (int d4 = 0; d4 < 16; d4++) {
                    float4 vv = vr[d4];            // uniform addr -> broadcast
                    o[d4 * 4 + 0] += pj * vv.x;
                    o[d4 * 4 + 1] += pj * vv.y;
                    o[d4 * 4 + 2] += pj * vv.z;
                    o[d4 * 4 + 3] += pj * vv.w;
                }
            }
            mrun = tmax;
        }
    }

    const float inv = 1.f / lrun;
    float* orow = g_ao + ((size_t)bh * Ss + qi) * HD;
#pragma unroll
    for (int d = 0; d < 64; d++) orow[d] = o[d] * inv;
}

// ---------------------------------------------------------------------------
// Kernel 3: output projection.  out[M,D] = AO[M,D] @ Wp[D,D] + b,
// gathering A from [B,H,S,hd] head layout.
// ---------------------------------------------------------------------------
__global__ void __launch_bounds__(256) proj_gemm(const float* __restrict__ Wp,
                                                 const float* __restrict__ bias,
                                                 float* __restrict__ out)
{
    __shared__ float As[16][68];
    __shared__ float Bs[16][64];

    const int bm = blockIdx.y * 64;
    const int bn = blockIdx.x * 64;
    const int tid = threadIdx.x;
    const int ty = tid >> 4, tx = tid & 15;
    const int arow = tid >> 2, ac = (tid & 3) * 4;
    const int brow = tid >> 4, bc = (tid & 15) * 4;

    float acc[4][4] = {};

    for (int k0 = 0; k0 < Dd; k0 += 16) {
        const int m = bm + arow;
        const int k = k0 + ac;                 // multiple of 4, stays in one head chunk
        const int b = m / Ss, s = m % Ss;
        const int h = k / HD, dd = k % HD;
        float4 a = *(const float4*)(g_ao + ((size_t)(b * Hh + h) * Ss + s) * HD + dd);
        As[ac + 0][arow] = a.x;
        As[ac + 1][arow] = a.y;
        As[ac + 2][arow] = a.z;
        As[ac + 3][arow] = a.w;
        *(float4*)&Bs[brow][bc] =
            *(const float4*)(Wp + (size_t)(k0 + brow) * Dd + bn + bc);
        __syncthreads();
#pragma unroll
        for (int kk = 0; kk < 16; kk++) {
            float4 av = *(const float4*)&As[kk][ty * 4];
            float4 bv = *(const float4*)&Bs[kk][tx * 4];
            acc[0][0] += av.x * bv.x; acc[0][1] += av.x * bv.y;
            acc[0][2] += av.x * bv.z; acc[0][3] += av.x * bv.w;
            acc[1][0] += av.y * bv.x; acc[1][1] += av.y * bv.y;
            acc[1][2] += av.y * bv.z; acc[1][3] += av.y * bv.w;
            acc[2][0] += av.z * bv.x; acc[2][1] += av.z * bv.y;
            acc[2][2] += av.z * bv.z; acc[2][3] += av.z * bv.w;
            acc[3][0] += av.w * bv.x; acc[3][1] += av.w * bv.y;
            acc[3][2] += av.w * bv.z; acc[3][3] += av.w * bv.w;
        }
        __syncthreads();
    }

#pragma unroll
    for (int i = 0; i < 4; i++) {
        const int m = bm + ty * 4 + i;
#pragma unroll
        for (int j = 0; j < 4; j++) {
            const int n = bn + tx * 4 + j;
            out[(size_t)m * Dd + n] = acc[i][j] + bias[n];
        }
    }
}

// ---------------------------------------------------------------------------
extern "C" void kernel_launch(void* const* d_in, const int* in_sizes, int n_in,
                              void* d_out, int out_size)
{
    const float* hs  = (const float*)d_in[0];   // hidden_states [B,S,D]
    const float* caw = (const float*)d_in[1];   // c_attn_w [D,3D]
    const float* cab = (const float*)d_in[2];   // c_attn_b [3D]
    const float* cpw = (const float*)d_in[3];   // c_proj_w [D,D]
    const float* cpb = (const float*)d_in[4];   // c_proj_b [D]
    float* out = (float*)d_out;                 // [B,S,D] fp32

    qkv_gemm<<<dim3(N3 / 64, Mm / 64), 256>>>(hs, caw, cab);
    attn_kernel<<<dim3(Ss / 128, Bb * Hh), 128>>>();
    proj_gemm<<<dim3(Dd / 64, Mm / 64), 256>>>(cpw, cpb, out);
}

// round 3
// speedup vs baseline: 1.3880x; 1.3880x over previous
#include <cuda_runtime.h>
#include <math.h>

#define Bb 2
#define Ss 2048
#define Dd 1024
#define Hh 16
#define HD 64
#define Mm (Bb*Ss)      /* 4096 */
#define N3 (3*Dd)       /* 3072 */

// Scratch: q,k,v,attn_out in [B,H,S,hd] layout.
__device__ float g_q [Bb*Hh*Ss*HD];
__device__ float g_k [Bb*Hh*Ss*HD];
__device__ float g_v [Bb*Hh*Ss*HD];
__device__ float g_ao[Bb*Hh*Ss*HD];

__device__ __forceinline__ unsigned f2tf(float x) {
    unsigned y;
    asm("cvt.rna.tf32.f32 %0, %1;" : "=r"(y) : "f"(x));
    return y;
}

__device__ __forceinline__ void mma_tf32(float c[4],
                                         unsigned a0, unsigned a1, unsigned a2, unsigned a3,
                                         unsigned b0, unsigned b1) {
    asm volatile(
        "mma.sync.aligned.m16n8k8.row.col.f32.tf32.tf32.f32 "
        "{%0,%1,%2,%3},{%4,%5,%6,%7},{%8,%9},{%0,%1,%2,%3};\n"
        : "+f"(c[0]), "+f"(c[1]), "+f"(c[2]), "+f"(c[3])
        : "r"(a0), "r"(a1), "r"(a2), "r"(a3), "r"(b0), "r"(b1));
}

// ---------------------------------------------------------------------------
// Kernel 1: QKV GEMM via tf32 mma.  C[M,3D] = X[M,D] @ W[D,3D] + b,
// scattered to q/k/v [B,H,S,hd] layout.
// Tile BM=128, BN=64, BK=16; 8 warps, each 32x32 (2 m-frags x 4 n-frags).
// ---------------------------------------------------------------------------
__global__ void __launch_bounds__(256) qkv_gemm(const float* __restrict__ X,
                                                const float* __restrict__ W,
                                                const float* __restrict__ bias)
{
    __shared__ unsigned As[128][20];   // [m][k], pad 16->20 (frag reads conflict-free)
    __shared__ unsigned Bs[16][72];    // [k][n], pad 64->72 (frag reads conflict-free)

    const int tid  = threadIdx.x;
    const int warp = tid >> 5, lane = tid & 31;
    const int wm = warp >> 1, wn = warp & 1;
    const int gid = lane >> 2, tig = lane & 3;
    const int bm = blockIdx.y * 128, bn = blockIdx.x * 64;

    float c[2][4][4] = {};

    for (int k0 = 0; k0 < Dd; k0 += 16) {
        // stage A (128x16): 512 float4, 2 per thread
#pragma unroll
        for (int i = 0; i < 2; i++) {
            const int idx = tid + i * 256;
            const int row = idx >> 2, cg = (idx & 3) * 4;
            float4 a = *(const float4*)(X + (size_t)(bm + row) * Dd + k0 + cg);
            uint4 u = { f2tf(a.x), f2tf(a.y), f2tf(a.z), f2tf(a.w) };
            *(uint4*)&As[row][cg] = u;
        }
        // stage B (16x64): 256 float4, 1 per thread
        {
            const int r = tid >> 4, cn = (tid & 15) * 4;
            float4 b = *(const float4*)(W + (size_t)(k0 + r) * N3 + bn + cn);
            uint4 u = { f2tf(b.x), f2tf(b.y), f2tf(b.z), f2tf(b.w) };
            *(uint4*)&Bs[r][cn] = u;
        }
        __syncthreads();

#pragma unroll
        for (int ks = 0; ks < 2; ks++) {
            const int kb = ks * 8;
            unsigned af[2][4];
#pragma unroll
            for (int mf = 0; mf < 2; mf++) {
                const int rb = wm * 32 + mf * 16 + gid;
                af[mf][0] = As[rb    ][kb + tig];
                af[mf][1] = As[rb + 8][kb + tig];
                af[mf][2] = As[rb    ][kb + tig + 4];
                af[mf][3] = As[rb + 8][kb + tig + 4];
            }
#pragma unroll
            for (int nf = 0; nf < 4; nf++) {
                const int cb = wn * 32 + nf * 8 + gid;
                unsigned b0 = Bs[kb + tig    ][cb];
                unsigned b1 = Bs[kb + tig + 4][cb];
                mma_tf32(c[0][nf], af[0][0], af[0][1], af[0][2], af[0][3], b0, b1);
                mma_tf32(c[1][nf], af[1][0], af[1][1], af[1][2], af[1][3], b0, b1);
            }
        }
        __syncthreads();
    }

    // Epilogue: bias + scatter into q/k/v head layout.
    const int which = bn / Dd;              // 0=q 1=k 2=v
    const int h = (bn % Dd) / HD;
    float* dst = (which == 0) ? g_q : ((which == 1) ? g_k : g_v);
#pragma unroll
    for (int mf = 0; mf < 2; mf++) {
#pragma unroll
        for (int nf = 0; nf < 4; nf++) {
            const int ncol = wn * 32 + nf * 8 + 2 * tig;
            const float bi0 = bias[bn + ncol], bi1 = bias[bn + ncol + 1];
#pragma unroll
            for (int rr = 0; rr < 2; rr++) {
                const int m = bm + wm * 32 + mf * 16 + gid + rr * 8;
                const int b = m / Ss, s = m % Ss;
                float* drow = dst + ((size_t)(b * Hh + h) * Ss + s) * HD;
                drow[ncol]     = c[mf][nf][rr * 2]     + bi0;
                drow[ncol + 1] = c[mf][nf][rr * 2 + 1] + bi1;
            }
        }
    }
}

// ---------------------------------------------------------------------------
// Kernel 2: causal flash attention, fp32 SIMT (unchanged this round).
// ---------------------------------------------------------------------------
__global__ void __launch_bounds__(128) attn_kernel()
{
    __shared__ float Ks[32 * 64];
    __shared__ float Vs[32 * 64];

    const int bh = blockIdx.y;
    const int q0 = blockIdx.x * 128;
    const int tid = threadIdx.x;
    const int qi = q0 + tid;

    const float* qrow = g_q + ((size_t)bh * Ss + qi) * HD;
    float q[64], o[64];
#pragma unroll
    for (int d = 0; d < 64; d++) { q[d] = qrow[d] * 0.125f; o[d] = 0.f; }

    float mrun = -1e30f, lrun = 0.f;
    const int ntiles = (q0 + 128) / 32;

    for (int kt = 0; kt < ntiles; kt++) {
        const int k0 = kt * 32;
        const float4* Kg = (const float4*)(g_k + ((size_t)bh * Ss + k0) * HD);
        const float4* Vg = (const float4*)(g_v + ((size_t)bh * Ss + k0) * HD);
        __syncthreads();
#pragma unroll
        for (int i = 0; i < 4; i++) {
            const int idx = tid + i * 128;
            ((float4*)Ks)[idx] = Kg[idx];
            ((float4*)Vs)[idx] = Vg[idx];
        }
        __syncthreads();

        if (k0 <= qi) {
            float p[32];
            float tmax = mrun;
#pragma unroll
            for (int j = 0; j < 32; j++) {
                const float4* kr = (const float4*)&Ks[j * 64];
                float s0 = 0.f, s1 = 0.f, s2 = 0.f, s3 = 0.f;
#pragma unroll
                for (int d4 = 0; d4 < 16; d4++) {
                    float4 kv = kr[d4];
                    s0 += q[d4 * 4 + 0] * kv.x;
                    s1 += q[d4 * 4 + 1] * kv.y;
                    s2 += q[d4 * 4 + 2] * kv.z;
                    s3 += q[d4 * 4 + 3] * kv.w;
                }
                float s = (s0 + s1) + (s2 + s3);
                if (k0 + j > qi) s = -1e30f;
                p[j] = s;
                tmax = fmaxf(tmax, s);
            }
            const float corr = __expf(mrun - tmax);
            lrun *= corr;
#pragma unroll
            for (int d = 0; d < 64; d++) o[d] *= corr;
            float lsum = 0.f;
#pragma unroll
            for (int j = 0; j < 32; j++) {
                const float pj = __expf(p[j] - tmax);
                p[j] = pj;
                lsum += pj;
            }
            lrun += lsum;
#pragma unroll
            for (int j = 0; j < 32; j++) {
                const float pj = p[j];
                const float4* vr = (const float4*)&Vs[j * 64];
#pragma unroll
                for (int d4 = 0; d4 < 16; d4++) {
                    float4 vv = vr[d4];
                    o[d4 * 4 + 0] += pj * vv.x;
                    o[d4 * 4 + 1] += pj * vv.y;
                    o[d4 * 4 + 2] += pj * vv.z;
                    o[d4 * 4 + 3] += pj * vv.w;
                }
            }
            mrun = tmax;
        }
    }

    const float inv = 1.f / lrun;
    float* orow = g_ao + ((size_t)bh * Ss + qi) * HD;
#pragma unroll
    for (int d = 0; d < 64; d++) orow[d] = o[d] * inv;
}

// ---------------------------------------------------------------------------
// Kernel 3: output projection via tf32 mma.  out = AO @ Wp + b, A gathered
// from [B,H,S,hd] head layout.  Same tiling as qkv_gemm.
// ---------------------------------------------------------------------------
__global__ void __launch_bounds__(256) proj_gemm(const float* __restrict__ Wp,
                                                 const float* __restrict__ bias,
                                                 float* __restrict__ out)
{
    __shared__ unsigned As[128][20];
    __shared__ unsigned Bs[16][72];

    const int tid  = threadIdx.x;
    const int warp = tid >> 5, lane = tid & 31;
    const int wm = warp >> 1, wn = warp & 1;
    const int gid = lane >> 2, tig = lane & 3;
    const int bm = blockIdx.y * 128, bn = blockIdx.x * 64;

    float c[2][4][4] = {};

    for (int k0 = 0; k0 < Dd; k0 += 16) {
#pragma unroll
        for (int i = 0; i < 2; i++) {
            const int idx = tid + i * 256;
            const int row = idx >> 2, cg = (idx & 3) * 4;
            const int m = bm + row;
            const int k = k0 + cg;               // stays within one head chunk
            const int b = m / Ss, s = m % Ss;
            const int h = k / HD, dd = k % HD;
            float4 a = *(const float4*)(g_ao + ((size_t)(b * Hh + h) * Ss + s) * HD + dd);
            uint4 u = { f2tf(a.x), f2tf(a.y), f2tf(a.z), f2tf(a.w) };
            *(uint4*)&As[row][cg] = u;
        }
        {
            const int r = tid >> 4, cn = (tid & 15) * 4;
            float4 b = *(const float4*)(Wp + (size_t)(k0 + r) * Dd + bn + cn);
            uint4 u = { f2tf(b.x), f2tf(b.y), f2tf(b.z), f2tf(b.w) };
            *(uint4*)&Bs[r][cn] = u;
        }
        __syncthreads();

#pragma unroll
        for (int ks = 0; ks < 2; ks++) {
            const int kb = ks * 8;
            unsigned af[2][4];
#pragma unroll
            for (int mf = 0; mf < 2; mf++) {
                const int rb = wm * 32 + mf * 16 + gid;
                af[mf][0] = As[rb    ][kb + tig];
                af[mf][1] = As[rb + 8][kb + tig];
                af[mf][2] = As[rb    ][kb + tig + 4];
                af[mf][3] = As[rb + 8][kb + tig + 4];
            }
#pragma unroll
            for (int nf = 0; nf < 4; nf++) {
                const int cb = wn * 32 + nf * 8 + gid;
                unsigned b0 = Bs[kb + tig    ][cb];
                unsigned b1 = Bs[kb + tig + 4][cb];
                mma_tf32(c[0][nf], af[0][0], af[0][1], af[0][2], af[0][3], b0, b1);
                mma_tf32(c[1][nf], af[1][0], af[1][1], af[1][2], af[1][3], b0, b1);
            }
        }
        __syncthreads();
    }

#pragma unroll
    for (int mf = 0; mf < 2; mf++) {
#pragma unroll
        for (int nf = 0; nf < 4; nf++) {
            const int ncol = wn * 32 + nf * 8 + 2 * tig;
            const float bi0 = bias[bn + ncol], bi1 = bias[bn + ncol + 1];
#pragma unroll
            for (int rr = 0; rr < 2; rr++) {
                const int m = bm + wm * 32 + mf * 16 + gid + rr * 8;
                out[(size_t)m * Dd + bn + ncol]     = c[mf][nf][rr * 2]     + bi0;
                out[(size_t)m * Dd + bn + ncol + 1] = c[mf][nf][rr * 2 + 1] + bi1;
            }
        }
    }
}

// ---------------------------------------------------------------------------
extern "C" void kernel_launch(void* const* d_in, const int* in_sizes, int n_in,
                              void* d_out, int out_size)
{
    const float* hs  = (const float*)d_in[0];   // hidden_states [B,S,D]
    const float* caw = (const float*)d_in[1];   // c_attn_w [D,3D]
    const float* cab = (const float*)d_in[2];   // c_attn_b [3D]
    const float* cpw = (const float*)d_in[3];   // c_proj_w [D,D]
    const float* cpb = (const float*)d_in[4];   // c_proj_b [D]
    float* out = (float*)d_out;                 // [B,S,D] fp32

    qkv_gemm<<<dim3(N3 / 64, Mm / 128), 256>>>(hs, caw, cab);
    attn_kernel<<<dim3(Ss / 128, Bb * Hh), 128>>>();
    proj_gemm<<<dim3(Dd / 64, Mm / 128), 256>>>(cpw, cpb, out);
}

// round 4
// speedup vs baseline: 3.4898x; 2.5143x over previous
#include <cuda_runtime.h>
#include <math.h>

#define Bb 2
#define Ss 2048
#define Dd 1024
#define Hh 16
#define HD 64
#define Mm (Bb*Ss)      /* 4096 */
#define N3 (3*Dd)       /* 3072 */

// Scratch: q,k,v,attn_out in [B,H,S,hd] layout.
__device__ float g_q [Bb*Hh*Ss*HD];
__device__ float g_k [Bb*Hh*Ss*HD];
__device__ float g_v [Bb*Hh*Ss*HD];
__device__ float g_ao[Bb*Hh*Ss*HD];

__device__ __forceinline__ unsigned f2tf(float x) {
    unsigned y;
    asm("cvt.rna.tf32.f32 %0, %1;" : "=r"(y) : "f"(x));
    return y;
}

__device__ __forceinline__ void mma_tf32(float c[4],
                                         unsigned a0, unsigned a1, unsigned a2, unsigned a3,
                                         unsigned b0, unsigned b1) {
    asm volatile(
        "mma.sync.aligned.m16n8k8.row.col.f32.tf32.tf32.f32 "
        "{%0,%1,%2,%3},{%4,%5,%6,%7},{%8,%9},{%0,%1,%2,%3};\n"
        : "+f"(c[0]), "+f"(c[1]), "+f"(c[2]), "+f"(c[3])
        : "r"(a0), "r"(a1), "r"(a2), "r"(a3), "r"(b0), "r"(b1));
}

// ---------------------------------------------------------------------------
// Kernel 1: QKV GEMM via tf32 mma (unchanged from R3).
// ---------------------------------------------------------------------------
__global__ void __launch_bounds__(256) qkv_gemm(const float* __restrict__ X,
                                                const float* __restrict__ W,
                                                const float* __restrict__ bias)
{
    __shared__ unsigned As[128][20];
    __shared__ unsigned Bs[16][72];

    const int tid  = threadIdx.x;
    const int warp = tid >> 5, lane = tid & 31;
    const int wm = warp >> 1, wn = warp & 1;
    const int gid = lane >> 2, tig = lane & 3;
    const int bm = blockIdx.y * 128, bn = blockIdx.x * 64;

    float c[2][4][4] = {};

    for (int k0 = 0; k0 < Dd; k0 += 16) {
#pragma unroll
        for (int i = 0; i < 2; i++) {
            const int idx = tid + i * 256;
            const int row = idx >> 2, cg = (idx & 3) * 4;
            float4 a = *(const float4*)(X + (size_t)(bm + row) * Dd + k0 + cg);
            uint4 u = { f2tf(a.x), f2tf(a.y), f2tf(a.z), f2tf(a.w) };
            *(uint4*)&As[row][cg] = u;
        }
        {
            const int r = tid >> 4, cn = (tid & 15) * 4;
            float4 b = *(const float4*)(W + (size_t)(k0 + r) * N3 + bn + cn);
            uint4 u = { f2tf(b.x), f2tf(b.y), f2tf(b.z), f2tf(b.w) };
            *(uint4*)&Bs[r][cn] = u;
        }
        __syncthreads();

#pragma unroll
        for (int ks = 0; ks < 2; ks++) {
            const int kb = ks * 8;
            unsigned af[2][4];
#pragma unroll
            for (int mf = 0; mf < 2; mf++) {
                const int rb = wm * 32 + mf * 16 + gid;
                af[mf][0] = As[rb    ][kb + tig];
                af[mf][1] = As[rb + 8][kb + tig];
                af[mf][2] = As[rb    ][kb + tig + 4];
                af[mf][3] = As[rb + 8][kb + tig + 4];
            }
#pragma unroll
            for (int nf = 0; nf < 4; nf++) {
                const int cb = wn * 32 + nf * 8 + gid;
                unsigned b0 = Bs[kb + tig    ][cb];
                unsigned b1 = Bs[kb + tig + 4][cb];
                mma_tf32(c[0][nf], af[0][0], af[0][1], af[0][2], af[0][3], b0, b1);
                mma_tf32(c[1][nf], af[1][0], af[1][1], af[1][2], af[1][3], b0, b1);
            }
        }
        __syncthreads();
    }

    const int which = bn / Dd;
    const int h = (bn % Dd) / HD;
    float* dst = (which == 0) ? g_q : ((which == 1) ? g_k : g_v);
#pragma unroll
    for (int mf = 0; mf < 2; mf++) {
#pragma unroll
        for (int nf = 0; nf < 4; nf++) {
            const int ncol = wn * 32 + nf * 8 + 2 * tig;
            const float bi0 = bias[bn + ncol], bi1 = bias[bn + ncol + 1];
#pragma unroll
            for (int rr = 0; rr < 2; rr++) {
                const int m = bm + wm * 32 + mf * 16 + gid + rr * 8;
                const int b = m / Ss, s = m % Ss;
                float* drow = dst + ((size_t)(b * Hh + h) * Ss + s) * HD;
                drow[ncol]     = c[mf][nf][rr * 2]     + bi0;
                drow[ncol + 1] = c[mf][nf][rr * 2 + 1] + bi1;
            }
        }
    }
}

// ---------------------------------------------------------------------------
// Kernel 2: causal flash attention via tf32 mma.
// Grid (S/64, B*H), 128 threads (4 warps).  Block: 64 q-rows; k-tiles of 32.
// Warp w owns q-rows [q0+16w, q0+16w+16).  S=Q.K^T and O+=P.V both m16n8k8.
// P round-trips through per-warp-private smem rows (no block sync needed).
// ---------------------------------------------------------------------------
__global__ void __launch_bounds__(128) attn_mma()
{
    __shared__ unsigned Qs[64][68];   // [row][hd] pad: frag reads conflict-free
    __shared__ unsigned Ks[32][68];   // [key][hd]
    __shared__ unsigned Vs[32][72];   // [key][hd] pad 72: B-frag rows-by-tig
    __shared__ unsigned Ps[64][36];   // [row][key]

    const int bh = blockIdx.y;
    const int qt = gridDim.x - 1 - (int)blockIdx.x;   // heaviest blocks first
    const int q0 = qt * 64;
    const int tid = threadIdx.x;
    const int warp = tid >> 5, lane = tid & 31;
    const int gid = lane >> 2, tig = lane & 3;
    const int w16 = warp * 16;

    // stage Q (pre-scaled by 1/sqrt(hd)) as tf32
    const float* Qg = g_q + ((size_t)bh * Ss + q0) * HD;
#pragma unroll
    for (int i = 0; i < 8; i++) {
        const int idx = tid + i * 128;            // 1024 float4
        const int r = idx >> 4, c = (idx & 15) * 4;
        float4 a = *(const float4*)(Qg + r * HD + c);
        uint4 u = { f2tf(a.x * 0.125f), f2tf(a.y * 0.125f),
                    f2tf(a.z * 0.125f), f2tf(a.w * 0.125f) };
        *(uint4*)&Qs[r][c] = u;
    }

    float o[8][4] = {};
    float m0 = -1e30f, m1 = -1e30f, l0 = 0.f, l1 = 0.f;

    const int nkt = (q0 + 64) / 32;
    for (int kt = 0; kt < nkt; kt++) {
        const int k0 = kt * 32;
        __syncthreads();
        const float* Kg = g_k + ((size_t)bh * Ss + k0) * HD;
        const float* Vg = g_v + ((size_t)bh * Ss + k0) * HD;
#pragma unroll
        for (int i = 0; i < 4; i++) {
            const int idx = tid + i * 128;        // 512 float4
            const int r = idx >> 4, c = (idx & 15) * 4;
            float4 a = *(const float4*)(Kg + r * HD + c);
            uint4 u = { f2tf(a.x), f2tf(a.y), f2tf(a.z), f2tf(a.w) };
            *(uint4*)&Ks[r][c] = u;
            float4 b = *(const float4*)(Vg + r * HD + c);
            uint4 v = { f2tf(b.x), f2tf(b.y), f2tf(b.z), f2tf(b.w) };
            *(uint4*)&Vs[r][c] = v;
        }
        __syncthreads();

        if (k0 <= q0 + w16 + 15) {                // warp participates
            float s[4][4] = {};
#pragma unroll
            for (int kk = 0; kk < 8; kk++) {
                const int kb = kk * 8;
                unsigned a0 = Qs[w16 + gid    ][kb + tig];
                unsigned a1 = Qs[w16 + gid + 8][kb + tig];
                unsigned a2 = Qs[w16 + gid    ][kb + tig + 4];
                unsigned a3 = Qs[w16 + gid + 8][kb + tig + 4];
#pragma unroll
                for (int nf = 0; nf < 4; nf++) {
                    const int cb = nf * 8 + gid;
                    unsigned b0 = Ks[cb][kb + tig];
                    unsigned b1 = Ks[cb][kb + tig + 4];
                    mma_tf32(s[nf], a0, a1, a2, a3, b0, b1);
                }
            }

            const int r0 = q0 + w16 + gid, r1 = r0 + 8;
            if (k0 + 32 > q0 + w16) {             // tile overlaps diagonal
#pragma unroll
                for (int nf = 0; nf < 4; nf++) {
                    const int cg = k0 + nf * 8 + 2 * tig;
                    if (cg     > r0) s[nf][0] = -1e30f;
                    if (cg + 1 > r0) s[nf][1] = -1e30f;
                    if (cg     > r1) s[nf][2] = -1e30f;
                    if (cg + 1 > r1) s[nf][3] = -1e30f;
                }
            }

            float tmax0 = -1e30f, tmax1 = -1e30f;
#pragma unroll
            for (int nf = 0; nf < 4; nf++) {
                tmax0 = fmaxf(tmax0, fmaxf(s[nf][0], s[nf][1]));
                tmax1 = fmaxf(tmax1, fmaxf(s[nf][2], s[nf][3]));
            }
            tmax0 = fmaxf(tmax0, __shfl_xor_sync(~0u, tmax0, 1));
            tmax0 = fmaxf(tmax0, __shfl_xor_sync(~0u, tmax0, 2));
            tmax1 = fmaxf(tmax1, __shfl_xor_sync(~0u, tmax1, 1));
            tmax1 = fmaxf(tmax1, __shfl_xor_sync(~0u, tmax1, 2));

            const float nm0 = fmaxf(m0, tmax0), nm1 = fmaxf(m1, tmax1);
            const float cr0 = __expf(m0 - nm0), cr1 = __expf(m1 - nm1);
            l0 *= cr0; l1 *= cr1;
#pragma unroll
            for (int nf = 0; nf < 8; nf++) {
                o[nf][0] *= cr0; o[nf][1] *= cr0;
                o[nf][2] *= cr1; o[nf][3] *= cr1;
            }
            m0 = nm0; m1 = nm1;

            float ls0 = 0.f, ls1 = 0.f;
#pragma unroll
            for (int nf = 0; nf < 4; nf++) {
                const float p0 = __expf(s[nf][0] - nm0);
                const float p1 = __expf(s[nf][1] - nm0);
                const float p2 = __expf(s[nf][2] - nm1);
                const float p3 = __expf(s[nf][3] - nm1);
                ls0 += p0 + p1; ls1 += p2 + p3;
                uint2 w01 = { f2tf(p0), f2tf(p1) };
                uint2 w23 = { f2tf(p2), f2tf(p3) };
                *(uint2*)&Ps[w16 + gid    ][nf * 8 + 2 * tig] = w01;
                *(uint2*)&Ps[w16 + gid + 8][nf * 8 + 2 * tig] = w23;
            }
            ls0 += __shfl_xor_sync(~0u, ls0, 1);
            ls0 += __shfl_xor_sync(~0u, ls0, 2);
            ls1 += __shfl_xor_sync(~0u, ls1, 1);
            ls1 += __shfl_xor_sync(~0u, ls1, 2);
            l0 += ls0; l1 += ls1;

            __syncwarp();                          // P visible within warp
#pragma unroll
            for (int kk = 0; kk < 4; kk++) {
                const int kb = kk * 8;
                unsigned a0 = Ps[w16 + gid    ][kb + tig];
                unsigned a1 = Ps[w16 + gid + 8][kb + tig];
                unsigned a2 = Ps[w16 + gid    ][kb + tig + 4];
                unsigned a3 = Ps[w16 + gid + 8][kb + tig + 4];
#pragma unroll
                for (int nf = 0; nf < 8; nf++) {
                    const int cb = nf * 8 + gid;
                    unsigned b0 = Vs[kb + tig    ][cb];
                    unsigned b1 = Vs[kb + tig + 4][cb];
                    mma_tf32(o[nf], a0, a1, a2, a3, b0, b1);
                }
            }
        }
    }

    const float inv0 = 1.f / l0, inv1 = 1.f / l1;
    float* O0 = g_ao + ((size_t)bh * Ss + q0 + w16 + gid) * HD;
    float* O1 = O0 + 8 * HD;
#pragma unroll
    for (int nf = 0; nf < 8; nf++) {
        const int cg = nf * 8 + 2 * tig;
        O0[cg]     = o[nf][0] * inv0;
        O0[cg + 1] = o[nf][1] * inv0;
        O1[cg]     = o[nf][2] * inv1;
        O1[cg + 1] = o[nf][3] * inv1;
    }
}

// ---------------------------------------------------------------------------
// Kernel 3: output projection via tf32 mma (unchanged from R3).
// ---------------------------------------------------------------------------
__global__ void __launch_bounds__(256) proj_gemm(const float* __restrict__ Wp,
                                                 const float* __restrict__ bias,
                                                 float* __restrict__ out)
{
    __shared__ unsigned As[128][20];
    __shared__ unsigned Bs[16][72];

    const int tid  = threadIdx.x;
    const int warp = tid >> 5, lane = tid & 31;
    const int wm = warp >> 1, wn = warp & 1;
    const int gid = lane >> 2, tig = lane & 3;
    const int bm = blockIdx.y * 128, bn = blockIdx.x * 64;

    float c[2][4][4] = {};

    for (int k0 = 0; k0 < Dd; k0 += 16) {
#pragma unroll
        for (int i = 0; i < 2; i++) {
            const int idx = tid + i * 256;
            const int row = idx >> 2, cg = (idx & 3) * 4;
            const int m = bm + row;
            const int k = k0 + cg;
            const int b = m / Ss, s = m % Ss;
            const int h = k / HD, dd = k % HD;
            float4 a = *(const float4*)(g_ao + ((size_t)(b * Hh + h) * Ss + s) * HD + dd);
            uint4 u = { f2tf(a.x), f2tf(a.y), f2tf(a.z), f2tf(a.w) };
            *(uint4*)&As[row][cg] = u;
        }
        {
            const int r = tid >> 4, cn = (tid & 15) * 4;
            float4 b = *(const float4*)(Wp + (size_t)(k0 + r) * Dd + bn + cn);
            uint4 u = { f2tf(b.x), f2tf(b.y), f2tf(b.z), f2tf(b.w) };
            *(uint4*)&Bs[r][cn] = u;
        }
        __syncthreads();

#pragma unroll
        for (int ks = 0; ks < 2; ks++) {
            const int kb = ks * 8;
            unsigned af[2][4];
#pragma unroll
            for (int mf = 0; mf < 2; mf++) {
                const int rb = wm * 32 + mf * 16 + gid;
                af[mf][0] = As[rb    ][kb + tig];
                af[mf][1] = As[rb + 8][kb + tig];
                af[mf][2] = As[rb    ][kb + tig + 4];
                af[mf][3] = As[rb + 8][kb + tig + 4];
            }
#pragma unroll
            for (int nf = 0; nf < 4; nf++) {
                const int cb = wn * 32 + nf * 8 + gid;
                unsigned b0 = Bs[kb + tig    ][cb];
                unsigned b1 = Bs[kb + tig + 4][cb];
                mma_tf32(c[0][nf], af[0][0], af[0][1], af[0][2], af[0][3], b0, b1);
                mma_tf32(c[1][nf], af[1][0], af[1][1], af[1][2], af[1][3], b0, b1);
            }
        }
        __syncthreads();
    }

#pragma unroll
    for (int mf = 0; mf < 2; mf++) {
#pragma unroll
        for (int nf = 0; nf < 4; nf++) {
            const int ncol = wn * 32 + nf * 8 + 2 * tig;
            const float bi0 = bias[bn + ncol], bi1 = bias[bn + ncol + 1];
#pragma unroll
            for (int rr = 0; rr < 2; rr++) {
                const int m = bm + wm * 32 + mf * 16 + gid + rr * 8;
                out[(size_t)m * Dd + bn + ncol]     = c[mf][nf][rr * 2]     + bi0;
                out[(size_t)m * Dd + bn + ncol + 1] = c[mf][nf][rr * 2 + 1] + bi1;
            }
        }
    }
}

// ---------------------------------------------------------------------------
extern "C" void kernel_launch(void* const* d_in, const int* in_sizes, int n_in,
                              void* d_out, int out_size)
{
    const float* hs  = (const float*)d_in[0];   // hidden_states [B,S,D]
    const float* caw = (const float*)d_in[1];   // c_attn_w [D,3D]
    const float* cab = (const float*)d_in[2];   // c_attn_b [3D]
    const float* cpw = (const float*)d_in[3];   // c_proj_w [D,D]
    const float* cpb = (const float*)d_in[4];   // c_proj_b [D]
    float* out = (float*)d_out;                 // [B,S,D] fp32

    qkv_gemm<<<dim3(N3 / 64, Mm / 128), 256>>>(hs, caw, cab);
    attn_mma<<<dim3(Ss / 64, Bb * Hh), 128>>>();
    proj_gemm<<<dim3(Dd / 64, Mm / 128), 256>>>(cpw, cpb, out);
}

// round 5
// speedup vs baseline: 3.8520x; 1.1038x over previous
#include <cuda_runtime.h>
#include <math.h>

#define Bb 2
#define Ss 2048
#define Dd 1024
#define Hh 16
#define HD 64
#define Mm (Bb*Ss)      /* 4096 */
#define N3 (3*Dd)       /* 3072 */

// Scratch: q,k,v,attn_out in [B,H,S,hd] layout.
__device__ float g_q [Bb*Hh*Ss*HD];
__device__ float g_k [Bb*Hh*Ss*HD];
__device__ float g_v [Bb*Hh*Ss*HD];
__device__ float g_ao[Bb*Hh*Ss*HD];

__device__ __forceinline__ unsigned f2tf(float x) {
    unsigned y;
    asm("cvt.rna.tf32.f32 %0, %1;" : "=r"(y) : "f"(x));
    return y;
}

__device__ __forceinline__ void mma_tf32(float c[4],
                                         unsigned a0, unsigned a1, unsigned a2, unsigned a3,
                                         unsigned b0, unsigned b1) {
    asm volatile(
        "mma.sync.aligned.m16n8k8.row.col.f32.tf32.tf32.f32 "
        "{%0,%1,%2,%3},{%4,%5,%6,%7},{%8,%9},{%0,%1,%2,%3};\n"
        : "+f"(c[0]), "+f"(c[1]), "+f"(c[2]), "+f"(c[3])
        : "r"(a0), "r"(a1), "r"(a2), "r"(a3), "r"(b0), "r"(b1));
}

// ===========================================================================
// GEMM core: BM=128, BN=128, BK=16, 256 threads, 8 warps (4x2), warp 32x64.
// Register-pipelined global loads; conflict-free padded smem.
// acc[2][8][4]: mf (m16) x nf (n8) x frag.
// ===========================================================================

// ---------------------------------------------------------------------------
// Kernel 1: QKV GEMM.  C[M,3D] = X[M,D] @ W[D,3D] + b, scattered to q/k/v.
// ---------------------------------------------------------------------------
__global__ void __launch_bounds__(256, 2) qkv_gemm(const float* __restrict__ X,
                                                   const float* __restrict__ W,
                                                   const float* __restrict__ bias)
{
    __shared__ unsigned As[128][20];    // [m][k]  pad 20: frag reads conflict-free
    __shared__ unsigned Bs[16][136];    // [k][n]  pad 136: frag reads conflict-free

    const int tid  = threadIdx.x;
    const int warp = tid >> 5, lane = tid & 31;
    const int wm = warp & 3, wn = warp >> 2;
    const int gid = lane >> 2, tig = lane & 3;
    const int bm = blockIdx.y * 128, bn = blockIdx.x * 128;

    const int arow = tid >> 2, acg = (tid & 3) * 4;    // A loader
    const int brow = tid >> 5, bcn = (tid & 31) * 4;   // B loader

    float acc[2][8][4] = {};
    float4 ra0, ra1, rb0, rb1;

    // prologue: load k0=0 tile
    ra0 = *(const float4*)(X + (size_t)(bm + arow)      * Dd + acg);
    ra1 = *(const float4*)(X + (size_t)(bm + arow + 64) * Dd + acg);
    rb0 = *(const float4*)(W + (size_t)(brow)     * N3 + bn + bcn);
    rb1 = *(const float4*)(W + (size_t)(brow + 8) * N3 + bn + bcn);

    for (int k0 = 0; k0 < Dd; k0 += 16) {
        // stage current tile
        {
            uint4 u0 = { f2tf(ra0.x), f2tf(ra0.y), f2tf(ra0.z), f2tf(ra0.w) };
            uint4 u1 = { f2tf(ra1.x), f2tf(ra1.y), f2tf(ra1.z), f2tf(ra1.w) };
            *(uint4*)&As[arow     ][acg] = u0;
            *(uint4*)&As[arow + 64][acg] = u1;
            uint4 v0 = { f2tf(rb0.x), f2tf(rb0.y), f2tf(rb0.z), f2tf(rb0.w) };
            uint4 v1 = { f2tf(rb1.x), f2tf(rb1.y), f2tf(rb1.z), f2tf(rb1.w) };
            *(uint4*)&Bs[brow    ][bcn] = v0;
            *(uint4*)&Bs[brow + 8][bcn] = v1;
        }
        __syncthreads();

        // issue next tile's global loads (latency hidden by compute below)
        const int kn = k0 + 16;
        if (kn < Dd) {
            ra0 = *(const float4*)(X + (size_t)(bm + arow)      * Dd + kn + acg);
            ra1 = *(const float4*)(X + (size_t)(bm + arow + 64) * Dd + kn + acg);
            rb0 = *(const float4*)(W + (size_t)(kn + brow)     * N3 + bn + bcn);
            rb1 = *(const float4*)(W + (size_t)(kn + brow + 8) * N3 + bn + bcn);
        }

#pragma unroll
        for (int ks = 0; ks < 2; ks++) {
            const int kb = ks * 8;
            unsigned af[2][4];
#pragma unroll
            for (int mf = 0; mf < 2; mf++) {
                const int rb = wm * 32 + mf * 16 + gid;
                af[mf][0] = As[rb    ][kb + tig];
                af[mf][1] = As[rb + 8][kb + tig];
                af[mf][2] = As[rb    ][kb + tig + 4];
                af[mf][3] = As[rb + 8][kb + tig + 4];
            }
#pragma unroll
            for (int nf = 0; nf < 8; nf++) {
                const int cb = wn * 64 + nf * 8 + gid;
                unsigned b0 = Bs[kb + tig    ][cb];
                unsigned b1 = Bs[kb + tig + 4][cb];
                mma_tf32(acc[0][nf], af[0][0], af[0][1], af[0][2], af[0][3], b0, b1);
                mma_tf32(acc[1][nf], af[1][0], af[1][1], af[1][2], af[1][3], b0, b1);
            }
        }
        __syncthreads();
    }

    // Epilogue: bias + scatter into q/k/v head layout.
    const int which = bn / Dd;              // 0=q 1=k 2=v (bn mult of 128)
    const int hbase = (bn % Dd) / HD;
    float* dst = (which == 0) ? g_q : ((which == 1) ? g_k : g_v);
#pragma unroll
    for (int mf = 0; mf < 2; mf++) {
#pragma unroll
        for (int nf = 0; nf < 8; nf++) {
            const int ncol = wn * 64 + nf * 8 + 2 * tig;
            const int h = hbase + (ncol >> 6);
            const int dd = ncol & 63;
            const float bi0 = bias[bn + ncol], bi1 = bias[bn + ncol + 1];
#pragma unroll
            for (int rr = 0; rr < 2; rr++) {
                const int m = bm + wm * 32 + mf * 16 + gid + rr * 8;
                const int b = m / Ss, s = m % Ss;
                float* drow = dst + ((size_t)(b * Hh + h) * Ss + s) * HD;
                drow[dd]     = acc[mf][nf][rr * 2]     + bi0;
                drow[dd + 1] = acc[mf][nf][rr * 2 + 1] + bi1;
            }
        }
    }
}

// ---------------------------------------------------------------------------
// Kernel 2: causal flash attention via tf32 mma (unchanged from R4).
// ---------------------------------------------------------------------------
__global__ void __launch_bounds__(128) attn_mma()
{
    __shared__ unsigned Qs[64][68];
    __shared__ unsigned Ks[32][68];
    __shared__ unsigned Vs[32][72];
    __shared__ unsigned Ps[64][36];

    const int bh = blockIdx.y;
    const int qt = gridDim.x - 1 - (int)blockIdx.x;
    const int q0 = qt * 64;
    const int tid = threadIdx.x;
    const int warp = tid >> 5, lane = tid & 31;
    const int gid = lane >> 2, tig = lane & 3;
    const int w16 = warp * 16;

    const float* Qg = g_q + ((size_t)bh * Ss + q0) * HD;
#pragma unroll
    for (int i = 0; i < 8; i++) {
        const int idx = tid + i * 128;
        const int r = idx >> 4, c = (idx & 15) * 4;
        float4 a = *(const float4*)(Qg + r * HD + c);
        uint4 u = { f2tf(a.x * 0.125f), f2tf(a.y * 0.125f),
                    f2tf(a.z * 0.125f), f2tf(a.w * 0.125f) };
        *(uint4*)&Qs[r][c] = u;
    }

    float o[8][4] = {};
    float m0 = -1e30f, m1 = -1e30f, l0 = 0.f, l1 = 0.f;

    const int nkt = (q0 + 64) / 32;
    for (int kt = 0; kt < nkt; kt++) {
        const int k0 = kt * 32;
        __syncthreads();
        const float* Kg = g_k + ((size_t)bh * Ss + k0) * HD;
        const float* Vg = g_v + ((size_t)bh * Ss + k0) * HD;
#pragma unroll
        for (int i = 0; i < 4; i++) {
            const int idx = tid + i * 128;
            const int r = idx >> 4, c = (idx & 15) * 4;
            float4 a = *(const float4*)(Kg + r * HD + c);
            uint4 u = { f2tf(a.x), f2tf(a.y), f2tf(a.z), f2tf(a.w) };
            *(uint4*)&Ks[r][c] = u;
            float4 b = *(const float4*)(Vg + r * HD + c);
            uint4 v = { f2tf(b.x), f2tf(b.y), f2tf(b.z), f2tf(b.w) };
            *(uint4*)&Vs[r][c] = v;
        }
        __syncthreads();

        if (k0 <= q0 + w16 + 15) {
            float s[4][4] = {};
#pragma unroll
            for (int kk = 0; kk < 8; kk++) {
                const int kb = kk * 8;
                unsigned a0 = Qs[w16 + gid    ][kb + tig];
                unsigned a1 = Qs[w16 + gid + 8][kb + tig];
                unsigned a2 = Qs[w16 + gid    ][kb + tig + 4];
                unsigned a3 = Qs[w16 + gid + 8][kb + tig + 4];
#pragma unroll
                for (int nf = 0; nf < 4; nf++) {
                    const int cb = nf * 8 + gid;
                    unsigned b0 = Ks[cb][kb + tig];
                    unsigned b1 = Ks[cb][kb + tig + 4];
                    mma_tf32(s[nf], a0, a1, a2, a3, b0, b1);
                }
            }

            const int r0 = q0 + w16 + gid, r1 = r0 + 8;
            if (k0 + 32 > q0 + w16) {
#pragma unroll
                for (int nf = 0; nf < 4; nf++) {
                    const int cg = k0 + nf * 8 + 2 * tig;
                    if (cg     > r0) s[nf][0] = -1e30f;
                    if (cg + 1 > r0) s[nf][1] = -1e30f;
                    if (cg     > r1) s[nf][2] = -1e30f;
                    if (cg + 1 > r1) s[nf][3] = -1e30f;
                }
            }

            float tmax0 = -1e30f, tmax1 = -1e30f;
#pragma unroll
            for (int nf = 0; nf < 4; nf++) {
                tmax0 = fmaxf(tmax0, fmaxf(s[nf][0], s[nf][1]));
                tmax1 = fmaxf(tmax1, fmaxf(s[nf][2], s[nf][3]));
            }
            tmax0 = fmaxf(tmax0, __shfl_xor_sync(~0u, tmax0, 1));
            tmax0 = fmaxf(tmax0, __shfl_xor_sync(~0u, tmax0, 2));
            tmax1 = fmaxf(tmax1, __shfl_xor_sync(~0u, tmax1, 1));
            tmax1 = fmaxf(tmax1, __shfl_xor_sync(~0u, tmax1, 2));

            const float nm0 = fmaxf(m0, tmax0), nm1 = fmaxf(m1, tmax1);
            const float cr0 = __expf(m0 - nm0), cr1 = __expf(m1 - nm1);
            l0 *= cr0; l1 *= cr1;
#pragma unroll
            for (int nf = 0; nf < 8; nf++) {
                o[nf][0] *= cr0; o[nf][1] *= cr0;
                o[nf][2] *= cr1; o[nf][3] *= cr1;
            }
            m0 = nm0; m1 = nm1;

            float ls0 = 0.f, ls1 = 0.f;
#pragma unroll
            for (int nf = 0; nf < 4; nf++) {
                const float p0 = __expf(s[nf][0] - nm0);
                const float p1 = __expf(s[nf][1] - nm0);
                const float p2 = __expf(s[nf][2] - nm1);
                const float p3 = __expf(s[nf][3] - nm1);
                ls0 += p0 + p1; ls1 += p2 + p3;
                uint2 w01 = { f2tf(p0), f2tf(p1) };
                uint2 w23 = { f2tf(p2), f2tf(p3) };
                *(uint2*)&Ps[w16 + gid    ][nf * 8 + 2 * tig] = w01;
                *(uint2*)&Ps[w16 + gid + 8][nf * 8 + 2 * tig] = w23;
            }
            ls0 += __shfl_xor_sync(~0u, ls0, 1);
            ls0 += __shfl_xor_sync(~0u, ls0, 2);
            ls1 += __shfl_xor_sync(~0u, ls1, 1);
            ls1 += __shfl_xor_sync(~0u, ls1, 2);
            l0 += ls0; l1 += ls1;

            __syncwarp();
#pragma unroll
            for (int kk = 0; kk < 4; kk++) {
                const int kb = kk * 8;
                unsigned a0 = Ps[w16 + gid    ][kb + tig];
                unsigned a1 = Ps[w16 + gid + 8][kb + tig];
                unsigned a2 = Ps[w16 + gid    ][kb + tig + 4];
                unsigned a3 = Ps[w16 + gid + 8][kb + tig + 4];
#pragma unroll
                for (int nf = 0; nf < 8; nf++) {
                    const int cb = nf * 8 + gid;
                    unsigned b0 = Vs[kb + tig    ][cb];
                    unsigned b1 = Vs[kb + tig + 4][cb];
                    mma_tf32(o[nf], a0, a1, a2, a3, b0, b1);
                }
            }
        }
    }

    const float inv0 = 1.f / l0, inv1 = 1.f / l1;
    float* O0 = g_ao + ((size_t)bh * Ss + q0 + w16 + gid) * HD;
    float* O1 = O0 + 8 * HD;
#pragma unroll
    for (int nf = 0; nf < 8; nf++) {
        const int cg = nf * 8 + 2 * tig;
        O0[cg]     = o[nf][0] * inv0;
        O0[cg + 1] = o[nf][1] * inv0;
        O1[cg]     = o[nf][2] * inv1;
        O1[cg + 1] = o[nf][3] * inv1;
    }
}

// ---------------------------------------------------------------------------
// Kernel 3: output projection.  out = AO @ Wp + b, A gathered from head
// layout.  Same BM=128/BN=128 pipelined core as qkv_gemm.
// ---------------------------------------------------------------------------
__global__ void __launch_bounds__(256, 2) proj_gemm(const float* __restrict__ Wp,
                                                    const float* __restrict__ bias,
                                                    float* __restrict__ out)
{
    __shared__ unsigned As[128][20];
    __shared__ unsigned Bs[16][136];

    const int tid  = threadIdx.x;
    const int warp = tid >> 5, lane = tid & 31;
    const int wm = warp & 3, wn = warp >> 2;
    const int gid = lane >> 2, tig = lane & 3;
    const int bm = blockIdx.y * 128, bn = blockIdx.x * 128;

    const int arow = tid >> 2, acg = (tid & 3) * 4;
    const int brow = tid >> 5, bcn = (tid & 31) * 4;

    // A-gather addressing (head layout); k-chunk stays within one head (HD%16==0)
    const int m0r = bm + arow;
    const int b0i = m0r / Ss, s0i = m0r % Ss;
    const int m1r = bm + arow + 64;
    const int b1i = m1r / Ss, s1i = m1r % Ss;

    float acc[2][8][4] = {};
    float4 ra0, ra1, rb0, rb1;

    {
        const int h = acg / HD, dd = acg % HD;
        ra0 = *(const float4*)(g_ao + ((size_t)(b0i * Hh + h) * Ss + s0i) * HD + dd);
        ra1 = *(const float4*)(g_ao + ((size_t)(b1i * Hh + h) * Ss + s1i) * HD + dd);
    }
    rb0 = *(const float4*)(Wp + (size_t)(brow)     * Dd + bn + bcn);
    rb1 = *(const float4*)(Wp + (size_t)(brow + 8) * Dd + bn + bcn);

    for (int k0 = 0; k0 < Dd; k0 += 16) {
        {
            uint4 u0 = { f2tf(ra0.x), f2tf(ra0.y), f2tf(ra0.z), f2tf(ra0.w) };
            uint4 u1 = { f2tf(ra1.x), f2tf(ra1.y), f2tf(ra1.z), f2tf(ra1.w) };
            *(uint4*)&As[arow     ][acg] = u0;
            *(uint4*)&As[arow + 64][acg] = u1;
            uint4 v0 = { f2tf(rb0.x), f2tf(rb0.y), f2tf(rb0.z), f2tf(rb0.w) };
            uint4 v1 = { f2tf(rb1.x), f2tf(rb1.y), f2tf(rb1.z), f2tf(rb1.w) };
            *(uint4*)&Bs[brow    ][bcn] = v0;
            *(uint4*)&Bs[brow + 8][bcn] = v1;
        }
        __syncthreads();

        const int kn = k0 + 16;
        if (kn < Dd) {
            const int k = kn + acg;
            const int h = k / HD, dd = k % HD;
            ra0 = *(const float4*)(g_ao + ((size_t)(b0i * Hh + h) * Ss + s0i) * HD + dd);
            ra1 = *(const float4*)(g_ao + ((size_t)(b1i * Hh + h) * Ss + s1i) * HD + dd);
            rb0 = *(const float4*)(Wp + (size_t)(kn + brow)     * Dd + bn + bcn);
            rb1 = *(const float4*)(Wp + (size_t)(kn + brow + 8) * Dd + bn + bcn);
        }

#pragma unroll
        for (int ks = 0; ks < 2; ks++) {
            const int kb = ks * 8;
            unsigned af[2][4];
#pragma unroll
            for (int mf = 0; mf < 2; mf++) {
                const int rb = wm * 32 + mf * 16 + gid;
                af[mf][0] = As[rb    ][kb + tig];
                af[mf][1] = As[rb + 8][kb + tig];
                af[mf][2] = As[rb    ][kb + tig + 4];
                af[mf][3] = As[rb + 8][kb + tig + 4];
            }
#pragma unroll
            for (int nf = 0; nf < 8; nf++) {
                const int cb = wn * 64 + nf * 8 + gid;
                unsigned b0 = Bs[kb + tig    ][cb];
                unsigned b1 = Bs[kb + tig + 4][cb];
                mma_tf32(acc[0][nf], af[0][0], af[0][1], af[0][2], af[0][3], b0, b1);
                mma_tf32(acc[1][nf], af[1][0], af[1][1], af[1][2], af[1][3], b0, b1);
            }
        }
        __syncthreads();
    }

#pragma unroll
    for (int mf = 0; mf < 2; mf++) {
#pragma unroll
        for (int nf = 0; nf < 8; nf++) {
            const int ncol = wn * 64 + nf * 8 + 2 * tig;
            const float bi0 = bias[bn + ncol], bi1 = bias[bn + ncol + 1];
#pragma unroll
            for (int rr = 0; rr < 2; rr++) {
                const int m = bm + wm * 32 + mf * 16 + gid + rr * 8;
                out[(size_t)m * Dd + bn + ncol]     = acc[mf][nf][rr * 2]     + bi0;
                out[(size_t)m * Dd + bn + ncol + 1] = acc[mf][nf][rr * 2 + 1] + bi1;
            }
        }
    }
}

// ---------------------------------------------------------------------------
extern "C" void kernel_launch(void* const* d_in, const int* in_sizes, int n_in,
                              void* d_out, int out_size)
{
    const float* hs  = (const float*)d_in[0];   // hidden_states [B,S,D]
    const float* caw = (const float*)d_in[1];   // c_attn_w [D,3D]
    const float* cab = (const float*)d_in[2];   // c_attn_b [3D]
    const float* cpw = (const float*)d_in[3];   // c_proj_w [D,D]
    const float* cpb = (const float*)d_in[4];   // c_proj_b [D]
    float* out = (float*)d_out;                 // [B,S,D] fp32

    qkv_gemm<<<dim3(N3 / 128, Mm / 128), 256>>>(hs, caw, cab);
    attn_mma<<<dim3(Ss / 64, Bb * Hh), 128>>>();
    proj_gemm<<<dim3(Dd / 128, Mm / 128), 256>>>(cpw, cpb, out);
}

// round 7
// speedup vs baseline: 3.9486x; 1.0251x over previous
#include <cuda_runtime.h>
#include <math.h>

#define Bb 2
#define Ss 2048
#define Dd 1024
#define Hh 16
#define HD 64
#define Mm (Bb*Ss)      /* 4096 */
#define N3 (3*Dd)       /* 3072 */

// Scratch: q,k,v,attn_out in [B,H,S,hd] layout.
__device__ float g_q [Bb*Hh*Ss*HD];
__device__ float g_k [Bb*Hh*Ss*HD];
__device__ float g_v [Bb*Hh*Ss*HD];
__device__ float g_ao[Bb*Hh*Ss*HD];

__device__ __forceinline__ unsigned f2tf(float x) {
    unsigned y;
    asm("cvt.rna.tf32.f32 %0, %1;" : "=r"(y) : "f"(x));
    return y;
}

__device__ __forceinline__ void mma_tf32(float c[4],
                                         unsigned a0, unsigned a1, unsigned a2, unsigned a3,
                                         unsigned b0, unsigned b1) {
    asm volatile(
        "mma.sync.aligned.m16n8k8.row.col.f32.tf32.tf32.f32 "
        "{%0,%1,%2,%3},{%4,%5,%6,%7},{%8,%9},{%0,%1,%2,%3};\n"
        : "+f"(c[0]), "+f"(c[1]), "+f"(c[2]), "+f"(c[3])
        : "r"(a0), "r"(a1), "r"(a2), "r"(a3), "r"(b0), "r"(b1));
}

// ===========================================================================
// GEMM core: BM=128, BN=128, BK=16, 256 threads, 8 warps (4x2), warp 32x64.
// Double-buffered smem: ONE barrier per iteration; STS overlaps mma.
// ===========================================================================

// ---------------------------------------------------------------------------
// Kernel 1: QKV GEMM.  C[M,3D] = X[M,D] @ W[D,3D] + b, scattered to q/k/v.
// ---------------------------------------------------------------------------
__global__ void __launch_bounds__(256, 2) qkv_gemm(const float* __restrict__ X,
                                                   const float* __restrict__ W,
                                                   const float* __restrict__ bias)
{
    __shared__ unsigned As[2][128][20];
    __shared__ unsigned Bs[2][16][136];

    const int tid  = threadIdx.x;
    const int warp = tid >> 5, lane = tid & 31;
    const int wm = warp & 3, wn = warp >> 2;
    const int gid = lane >> 2, tig = lane & 3;
    const int bm = blockIdx.y * 128, bn = blockIdx.x * 128;

    const int arow = tid >> 2, acg = (tid & 3) * 4;
    const int brow = tid >> 5, bcn = (tid & 31) * 4;

    float acc[2][8][4] = {};
    float4 ra0, ra1, rb0, rb1;

    // prologue: load + stage tile 0
    ra0 = *(const float4*)(X + (size_t)(bm + arow)      * Dd + acg);
    ra1 = *(const float4*)(X + (size_t)(bm + arow + 64) * Dd + acg);
    rb0 = *(const float4*)(W + (size_t)(brow)     * N3 + bn + bcn);
    rb1 = *(const float4*)(W + (size_t)(brow + 8) * N3 + bn + bcn);
    {
        uint4 u0 = { f2tf(ra0.x), f2tf(ra0.y), f2tf(ra0.z), f2tf(ra0.w) };
        uint4 u1 = { f2tf(ra1.x), f2tf(ra1.y), f2tf(ra1.z), f2tf(ra1.w) };
        *(uint4*)&As[0][arow     ][acg] = u0;
        *(uint4*)&As[0][arow + 64][acg] = u1;
        uint4 v0 = { f2tf(rb0.x), f2tf(rb0.y), f2tf(rb0.z), f2tf(rb0.w) };
        uint4 v1 = { f2tf(rb1.x), f2tf(rb1.y), f2tf(rb1.z), f2tf(rb1.w) };
        *(uint4*)&Bs[0][brow    ][bcn] = v0;
        *(uint4*)&Bs[0][brow + 8][bcn] = v1;
    }
    __syncthreads();

    int cur = 0;
    for (int k0 = 0; k0 < Dd; k0 += 16) {
        const int kn = k0 + 16;
        if (kn < Dd) {
            ra0 = *(const float4*)(X + (size_t)(bm + arow)      * Dd + kn + acg);
            ra1 = *(const float4*)(X + (size_t)(bm + arow + 64) * Dd + kn + acg);
            rb0 = *(const float4*)(W + (size_t)(kn + brow)     * N3 + bn + bcn);
            rb1 = *(const float4*)(W + (size_t)(kn + brow + 8) * N3 + bn + bcn);
        }

#pragma unroll
        for (int ks = 0; ks < 2; ks++) {
            const int kb = ks * 8;
            unsigned af[2][4];
#pragma unroll
            for (int mf = 0; mf < 2; mf++) {
                const int rb = wm * 32 + mf * 16 + gid;
                af[mf][0] = As[cur][rb    ][kb + tig];
                af[mf][1] = As[cur][rb + 8][kb + tig];
                af[mf][2] = As[cur][rb    ][kb + tig + 4];
                af[mf][3] = As[cur][rb + 8][kb + tig + 4];
            }
#pragma unroll
            for (int nf = 0; nf < 8; nf++) {
                const int cb = wn * 64 + nf * 8 + gid;
                unsigned b0 = Bs[cur][kb + tig    ][cb];
                unsigned b1 = Bs[cur][kb + tig + 4][cb];
                mma_tf32(acc[0][nf], af[0][0], af[0][1], af[0][2], af[0][3], b0, b1);
                mma_tf32(acc[1][nf], af[1][0], af[1][1], af[1][2], af[1][3], b0, b1);
            }
        }

        if (kn < Dd) {
            const int nxt = cur ^ 1;
            uint4 u0 = { f2tf(ra0.x), f2tf(ra0.y), f2tf(ra0.z), f2tf(ra0.w) };
            uint4 u1 = { f2tf(ra1.x), f2tf(ra1.y), f2tf(ra1.z), f2tf(ra1.w) };
            *(uint4*)&As[nxt][arow     ][acg] = u0;
            *(uint4*)&As[nxt][arow + 64][acg] = u1;
            uint4 v0 = { f2tf(rb0.x), f2tf(rb0.y), f2tf(rb0.z), f2tf(rb0.w) };
            uint4 v1 = { f2tf(rb1.x), f2tf(rb1.y), f2tf(rb1.z), f2tf(rb1.w) };
            *(uint4*)&Bs[nxt][brow    ][bcn] = v0;
            *(uint4*)&Bs[nxt][brow + 8][bcn] = v1;
            __syncthreads();
            cur = nxt;
        }
    }

    // Epilogue: bias + scatter into q/k/v head layout.
    const int which = bn / Dd;
    const int hbase = (bn % Dd) / HD;
    float* dst = (which == 0) ? g_q : ((which == 1) ? g_k : g_v);
#pragma unroll
    for (int mf = 0; mf < 2; mf++) {
#pragma unroll
        for (int nf = 0; nf < 8; nf++) {
            const int ncol = wn * 64 + nf * 8 + 2 * tig;
            const int h = hbase + (ncol >> 6);
            const int dd = ncol & 63;
            const float bi0 = bias[bn + ncol], bi1 = bias[bn + ncol + 1];
#pragma unroll
            for (int rr = 0; rr < 2; rr++) {
                const int m = bm + wm * 32 + mf * 16 + gid + rr * 8;
                const int b = m / Ss, s = m % Ss;
                float* drow = dst + ((size_t)(b * Hh + h) * Ss + s) * HD;
                drow[dd]     = acc[mf][nf][rr * 2]     + bi0;
                drow[dd + 1] = acc[mf][nf][rr * 2 + 1] + bi1;
            }
        }
    }
}

// ---------------------------------------------------------------------------
// Kernel 2: causal flash attention via tf32 mma.
// Register-prefetched K/V tiles (4 float4 each, full 32x64 coverage, LDG and
// STS use IDENTICAL coords).  Prefetch issues before compute of current tile.
// ---------------------------------------------------------------------------
__global__ void __launch_bounds__(128) attn_mma()
{
    __shared__ unsigned Qs[64][68];
    __shared__ unsigned Ks[32][68];
    __shared__ unsigned Vs[32][72];
    __shared__ unsigned Ps[64][36];

    const int bh = blockIdx.y;
    const int qt = gridDim.x - 1 - (int)blockIdx.x;
    const int q0 = qt * 64;
    const int tid = threadIdx.x;
    const int warp = tid >> 5, lane = tid & 31;
    const int gid = lane >> 2, tig = lane & 3;
    const int w16 = warp * 16;

    const float* Qg = g_q + ((size_t)bh * Ss + q0) * HD;
#pragma unroll
    for (int i = 0; i < 8; i++) {
        const int idx = tid + i * 128;
        const int r = idx >> 4, c = (idx & 15) * 4;
        float4 a = *(const float4*)(Qg + r * HD + c);
        uint4 u = { f2tf(a.x * 0.125f), f2tf(a.y * 0.125f),
                    f2tf(a.z * 0.125f), f2tf(a.w * 0.125f) };
        *(uint4*)&Qs[r][c] = u;
    }

    float o[8][4] = {};
    float m0 = -1e30f, m1 = -1e30f, l0 = 0.f, l1 = 0.f;

    const int nkt = (q0 + 64) / 32;

    // prologue: load tile 0 into regs (512 float4 each for K and V: 4/thread)
    float4 rk[4], rv[4];
#pragma unroll
    for (int i = 0; i < 4; i++) {
        const int idx = tid + i * 128;
        const int r = idx >> 4, c = (idx & 15) * 4;
        rk[i] = *(const float4*)(g_k + ((size_t)bh * Ss + r) * HD + c);
        rv[i] = *(const float4*)(g_v + ((size_t)bh * Ss + r) * HD + c);
    }

    for (int kt = 0; kt < nkt; kt++) {
        const int k0 = kt * 32;
        __syncthreads();   // prior tile's compute done reading Ks/Vs
#pragma unroll
        for (int i = 0; i < 4; i++) {
            const int idx = tid + i * 128;
            const int r = idx >> 4, c = (idx & 15) * 4;
            uint4 u = { f2tf(rk[i].x), f2tf(rk[i].y), f2tf(rk[i].z), f2tf(rk[i].w) };
            *(uint4*)&Ks[r][c] = u;
            uint4 v = { f2tf(rv[i].x), f2tf(rv[i].y), f2tf(rv[i].z), f2tf(rv[i].w) };
            *(uint4*)&Vs[r][c] = v;
        }
        __syncthreads();

        // prefetch next tile (latency hidden by compute below)
        if (kt + 1 < nkt) {
            const int kn0 = k0 + 32;
#pragma unroll
            for (int i = 0; i < 4; i++) {
                const int idx = tid + i * 128;
                const int r = idx >> 4, c = (idx & 15) * 4;
                rk[i] = *(const float4*)(g_k + ((size_t)bh * Ss + kn0 + r) * HD + c);
                rv[i] = *(const float4*)(g_v + ((size_t)bh * Ss + kn0 + r) * HD + c);
            }
        }

        if (k0 <= q0 + w16 + 15) {
            float s[4][4] = {};
#pragma unroll
            for (int kk = 0; kk < 8; kk++) {
                const int kb = kk * 8;
                unsigned a0 = Qs[w16 + gid    ][kb + tig];
                unsigned a1 = Qs[w16 + gid + 8][kb + tig];
                unsigned a2 = Qs[w16 + gid    ][kb + tig + 4];
                unsigned a3 = Qs[w16 + gid + 8][kb + tig + 4];
#pragma unroll
                for (int nf = 0; nf < 4; nf++) {
                    const int cb = nf * 8 + gid;
                    unsigned b0 = Ks[cb][kb + tig];
                    unsigned b1 = Ks[cb][kb + tig + 4];
                    mma_tf32(s[nf], a0, a1, a2, a3, b0, b1);
                }
            }

            const int r0 = q0 + w16 + gid, r1 = r0 + 8;
            if (k0 + 32 > q0 + w16) {
#pragma unroll
                for (int nf = 0; nf < 4; nf++) {
                    const int cg = k0 + nf * 8 + 2 * tig;
                    if (cg     > r0) s[nf][0] = -1e30f;
                    if (cg + 1 > r0) s[nf][1] = -1e30f;
                    if (cg     > r1) s[nf][2] = -1e30f;
                    if (cg + 1 > r1) s[nf][3] = -1e30f;
                }
            }

            float tmax0 = -1e30f, tmax1 = -1e30f;
#pragma unroll
            for (int nf = 0; nf < 4; nf++) {
                tmax0 = fmaxf(tmax0, fmaxf(s[nf][0], s[nf][1]));
                tmax1 = fmaxf(tmax1, fmaxf(s[nf][2], s[nf][3]));
            }
            tmax0 = fmaxf(tmax0, __shfl_xor_sync(~0u, tmax0, 1));
            tmax0 = fmaxf(tmax0, __shfl_xor_sync(~0u, tmax0, 2));
            tmax1 = fmaxf(tmax1, __shfl_xor_sync(~0u, tmax1, 1));
            tmax1 = fmaxf(tmax1, __shfl_xor_sync(~0u, tmax1, 2));

            const float nm0 = fmaxf(m0, tmax0), nm1 = fmaxf(m1, tmax1);
            const float cr0 = __expf(m0 - nm0), cr1 = __expf(m1 - nm1);
            l0 *= cr0; l1 *= cr1;
#pragma unroll
            for (int nf = 0; nf < 8; nf++) {
                o[nf][0] *= cr0; o[nf][1] *= cr0;
                o[nf][2] *= cr1; o[nf][3] *= cr1;
            }
            m0 = nm0; m1 = nm1;

            float ls0 = 0.f, ls1 = 0.f;
#pragma unroll
            for (int nf = 0; nf < 4; nf++) {
                const float p0 = __expf(s[nf][0] - nm0);
                const float p1 = __expf(s[nf][1] - nm0);
                const float p2 = __expf(s[nf][2] - nm1);
                const float p3 = __expf(s[nf][3] - nm1);
                ls0 += p0 + p1; ls1 += p2 + p3;
                uint2 w01 = { f2tf(p0), f2tf(p1) };
                uint2 w23 = { f2tf(p2), f2tf(p3) };
                *(uint2*)&Ps[w16 + gid    ][nf * 8 + 2 * tig] = w01;
                *(uint2*)&Ps[w16 + gid + 8][nf * 8 + 2 * tig] = w23;
            }
            ls0 += __shfl_xor_sync(~0u, ls0, 1);
            ls0 += __shfl_xor_sync(~0u, ls0, 2);
            ls1 += __shfl_xor_sync(~0u, ls1, 1);
            ls1 += __shfl_xor_sync(~0u, ls1, 2);
            l0 += ls0; l1 += ls1;

            __syncwarp();
#pragma unroll
            for (int kk = 0; kk < 4; kk++) {
                const int kb = kk * 8;
                unsigned a0 = Ps[w16 + gid    ][kb + tig];
                unsigned a1 = Ps[w16 + gid + 8][kb + tig];
                unsigned a2 = Ps[w16 + gid    ][kb + tig + 4];
                unsigned a3 = Ps[w16 + gid + 8][kb + tig + 4];
#pragma unroll
                for (int nf = 0; nf < 8; nf++) {
                    const int cb = nf * 8 + gid;
                    unsigned b0 = Vs[kb + tig    ][cb];
                    unsigned b1 = Vs[kb + tig + 4][cb];
                    mma_tf32(o[nf], a0, a1, a2, a3, b0, b1);
                }
            }
        }
    }

    const float inv0 = 1.f / l0, inv1 = 1.f / l1;
    float* O0 = g_ao + ((size_t)bh * Ss + q0 + w16 + gid) * HD;
    float* O1 = O0 + 8 * HD;
#pragma unroll
    for (int nf = 0; nf < 8; nf++) {
        const int cg = nf * 8 + 2 * tig;
        O0[cg]     = o[nf][0] * inv0;
        O0[cg + 1] = o[nf][1] * inv0;
        O1[cg]     = o[nf][2] * inv1;
        O1[cg + 1] = o[nf][3] * inv1;
    }
}

// ---------------------------------------------------------------------------
// Kernel 3: output projection, double-buffered like qkv_gemm.
// ---------------------------------------------------------------------------
__global__ void __launch_bounds__(256, 2) proj_gemm(const float* __restrict__ Wp,
                                                    const float* __restrict__ bias,
                                                    float* __restrict__ out)
{
    __shared__ unsigned As[2][128][20];
    __shared__ unsigned Bs[2][16][136];

    const int tid  = threadIdx.x;
    const int warp = tid >> 5, lane = tid & 31;
    const int wm = warp & 3, wn = warp >> 2;
    const int gid = lane >> 2, tig = lane & 3;
    const int bm = blockIdx.y * 128, bn = blockIdx.x * 128;

    const int arow = tid >> 2, acg = (tid & 3) * 4;
    const int brow = tid >> 5, bcn = (tid & 31) * 4;

    const int m0r = bm + arow;
    const int b0i = m0r / Ss, s0i = m0r % Ss;
    const int m1r = bm + arow + 64;
    const int b1i = m1r / Ss, s1i = m1r % Ss;

    float acc[2][8][4] = {};
    float4 ra0, ra1, rb0, rb1;

    {
        const int h = acg / HD, dd = acg % HD;
        ra0 = *(const float4*)(g_ao + ((size_t)(b0i * Hh + h) * Ss + s0i) * HD + dd);
        ra1 = *(const float4*)(g_ao + ((size_t)(b1i * Hh + h) * Ss + s1i) * HD + dd);
    }
    rb0 = *(const float4*)(Wp + (size_t)(brow)     * Dd + bn + bcn);
    rb1 = *(const float4*)(Wp + (size_t)(brow + 8) * Dd + bn + bcn);
    {
        uint4 u0 = { f2tf(ra0.x), f2tf(ra0.y), f2tf(ra0.z), f2tf(ra0.w) };
        uint4 u1 = { f2tf(ra1.x), f2tf(ra1.y), f2tf(ra1.z), f2tf(ra1.w) };
        *(uint4*)&As[0][arow     ][acg] = u0;
        *(uint4*)&As[0][arow + 64][acg] = u1;
        uint4 v0 = { f2tf(rb0.x), f2tf(rb0.y), f2tf(rb0.z), f2tf(rb0.w) };
        uint4 v1 = { f2tf(rb1.x), f2tf(rb1.y), f2tf(rb1.z), f2tf(rb1.w) };
        *(uint4*)&Bs[0][brow    ][bcn] = v0;
        *(uint4*)&Bs[0][brow + 8][bcn] = v1;
    }
    __syncthreads();

    int cur = 0;
    for (int k0 = 0; k0 < Dd; k0 += 16) {
        const int kn = k0 + 16;
        if (kn < Dd) {
            const int k = kn + acg;
            const int h = k / HD, dd = k % HD;
            ra0 = *(const float4*)(g_ao + ((size_t)(b0i * Hh + h) * Ss + s0i) * HD + dd);
            ra1 = *(const float4*)(g_ao + ((size_t)(b1i * Hh + h) * Ss + s1i) * HD + dd);
            rb0 = *(const float4*)(Wp + (size_t)(kn + brow)     * Dd + bn + bcn);
            rb1 = *(const float4*)(Wp + (size_t)(kn + brow + 8) * Dd + bn + bcn);
        }

#pragma unroll
        for (int ks = 0; ks < 2; ks++) {
            const int kb = ks * 8;
            unsigned af[2][4];
#pragma unroll
            for (int mf = 0; mf < 2; mf++) {
                const int rb = wm * 32 + mf * 16 + gid;
                af[mf][0] = As[cur][rb    ][kb + tig];
                af[mf][1] = As[cur][rb + 8][kb + tig];
                af[mf][2] = As[cur][rb    ][kb + tig + 4];
                af[mf][3] = As[cur][rb + 8][kb + tig + 4];
            }
#pragma unroll
            for (int nf = 0; nf < 8; nf++) {
                const int cb = wn * 64 + nf * 8 + gid;
                unsigned b0 = Bs[cur][kb + tig    ][cb];
                unsigned b1 = Bs[cur][kb + tig + 4][cb];
                mma_tf32(acc[0][nf], af[0][0], af[0][1], af[0][2], af[0][3], b0, b1);
                mma_tf32(acc[1][nf], af[1][0], af[1][1], af[1][2], af[1][3], b0, b1);
            }
        }

        if (kn < Dd) {
            const int nxt = cur ^ 1;
            uint4 u0 = { f2tf(ra0.x), f2tf(ra0.y), f2tf(ra0.z), f2tf(ra0.w) };
            uint4 u1 = { f2tf(ra1.x), f2tf(ra1.y), f2tf(ra1.z), f2tf(ra1.w) };
            *(uint4*)&As[nxt][arow     ][acg] = u0;
            *(uint4*)&As[nxt][arow + 64][acg] = u1;
            uint4 v0 = { f2tf(rb0.x), f2tf(rb0.y), f2tf(rb0.z), f2tf(rb0.w) };
            uint4 v1 = { f2tf(rb1.x), f2tf(rb1.y), f2tf(rb1.z), f2tf(rb1.w) };
            *(uint4*)&Bs[nxt][brow    ][bcn] = v0;
            *(uint4*)&Bs[nxt][brow + 8][bcn] = v1;
            __syncthreads();
            cur = nxt;
        }
    }

#pragma unroll
    for (int mf = 0; mf < 2; mf++) {
#pragma unroll
        for (int nf = 0; nf < 8; nf++) {
            const int ncol = wn * 64 + nf * 8 + 2 * tig;
            const float bi0 = bias[bn + ncol], bi1 = bias[bn + ncol + 1];
#pragma unroll
            for (int rr = 0; rr < 2; rr++) {
                const int m = bm + wm * 32 + mf * 16 + gid + rr * 8;
                out[(size_t)m * Dd + bn + ncol]     = acc[mf][nf][rr * 2]     + bi0;
                out[(size_t)m * Dd + bn + ncol + 1] = acc[mf][nf][rr * 2 + 1] + bi1;
            }
        }
    }
}

// ---------------------------------------------------------------------------
extern "C" void kernel_launch(void* const* d_in, const int* in_sizes, int n_in,
                              void* d_out, int out_size)
{
    const float* hs  = (const float*)d_in[0];   // hidden_states [B,S,D]
    const float* caw = (const float*)d_in[1];   // c_attn_w [D,3D]
    const float* cab = (const float*)d_in[2];   // c_attn_b [3D]
    const float* cpw = (const float*)d_in[3];   // c_proj_w [D,D]
    const float* cpb = (const float*)d_in[4];   // c_proj_b [D]
    float* out = (float*)d_out;                 // [B,S,D] fp32

    qkv_gemm<<<dim3(N3 / 128, Mm / 128), 256>>>(hs, caw, cab);
    attn_mma<<<dim3(Ss / 64, Bb * Hh), 128>>>();
    proj_gemm<<<dim3(Dd / 128, Mm / 128), 256>>>(cpw, cpb, out);
}

// round 8
// speedup vs baseline: 4.3038x; 1.0900x over previous
#include <cuda_runtime.h>
#include <math.h>

#define Bb 2
#define Ss 2048
#define Dd 1024
#define Hh 16
#define HD 64
#define Mm (Bb*Ss)      /* 4096 */
#define N3 (3*Dd)       /* 3072 */

// Scratch: q,k,v,attn_out in [B,H,S,hd] layout.
__device__ float g_q [Bb*Hh*Ss*HD];
__device__ float g_k [Bb*Hh*Ss*HD];
__device__ float g_v [Bb*Hh*Ss*HD];
__device__ float g_ao[Bb*Hh*Ss*HD];

__device__ __forceinline__ unsigned f2tf(float x) {
    unsigned y;
    asm("cvt.rna.tf32.f32 %0, %1;" : "=r"(y) : "f"(x));
    return y;
}

__device__ __forceinline__ void mma_tf32(float c[4],
                                         unsigned a0, unsigned a1, unsigned a2, unsigned a3,
                                         unsigned b0, unsigned b1) {
    asm volatile(
        "mma.sync.aligned.m16n8k8.row.col.f32.tf32.tf32.f32 "
        "{%0,%1,%2,%3},{%4,%5,%6,%7},{%8,%9},{%0,%1,%2,%3};\n"
        : "+f"(c[0]), "+f"(c[1]), "+f"(c[2]), "+f"(c[3])
        : "r"(a0), "r"(a1), "r"(a2), "r"(a3), "r"(b0), "r"(b1));
}

// ===========================================================================
// GEMM core (unchanged from R7): BM=128, BN=128, BK=16, 256 thr, 8 warps,
// warp 32x64, double-buffered smem.
// ===========================================================================

__global__ void __launch_bounds__(256, 2) qkv_gemm(const float* __restrict__ X,
                                                   const float* __restrict__ W,
                                                   const float* __restrict__ bias)
{
    __shared__ unsigned As[2][128][20];
    __shared__ unsigned Bs[2][16][136];

    const int tid  = threadIdx.x;
    const int warp = tid >> 5, lane = tid & 31;
    const int wm = warp & 3, wn = warp >> 2;
    const int gid = lane >> 2, tig = lane & 3;
    const int bm = blockIdx.y * 128, bn = blockIdx.x * 128;

    const int arow = tid >> 2, acg = (tid & 3) * 4;
    const int brow = tid >> 5, bcn = (tid & 31) * 4;

    float acc[2][8][4] = {};
    float4 ra0, ra1, rb0, rb1;

    ra0 = *(const float4*)(X + (size_t)(bm + arow)      * Dd + acg);
    ra1 = *(const float4*)(X + (size_t)(bm + arow + 64) * Dd + acg);
    rb0 = *(const float4*)(W + (size_t)(brow)     * N3 + bn + bcn);
    rb1 = *(const float4*)(W + (size_t)(brow + 8) * N3 + bn + bcn);
    {
        uint4 u0 = { f2tf(ra0.x), f2tf(ra0.y), f2tf(ra0.z), f2tf(ra0.w) };
        uint4 u1 = { f2tf(ra1.x), f2tf(ra1.y), f2tf(ra1.z), f2tf(ra1.w) };
        *(uint4*)&As[0][arow     ][acg] = u0;
        *(uint4*)&As[0][arow + 64][acg] = u1;
        uint4 v0 = { f2tf(rb0.x), f2tf(rb0.y), f2tf(rb0.z), f2tf(rb0.w) };
        uint4 v1 = { f2tf(rb1.x), f2tf(rb1.y), f2tf(rb1.z), f2tf(rb1.w) };
        *(uint4*)&Bs[0][brow    ][bcn] = v0;
        *(uint4*)&Bs[0][brow + 8][bcn] = v1;
    }
    __syncthreads();

    int cur = 0;
    for (int k0 = 0; k0 < Dd; k0 += 16) {
        const int kn = k0 + 16;
        if (kn < Dd) {
            ra0 = *(const float4*)(X + (size_t)(bm + arow)      * Dd + kn + acg);
            ra1 = *(const float4*)(X + (size_t)(bm + arow + 64) * Dd + kn + acg);
            rb0 = *(const float4*)(W + (size_t)(kn + brow)     * N3 + bn + bcn);
            rb1 = *(const float4*)(W + (size_t)(kn + brow + 8) * N3 + bn + bcn);
        }

#pragma unroll
        for (int ks = 0; ks < 2; ks++) {
            const int kb = ks * 8;
            unsigned af[2][4];
#pragma unroll
            for (int mf = 0; mf < 2; mf++) {
                const int rb = wm * 32 + mf * 16 + gid;
                af[mf][0] = As[cur][rb    ][kb + tig];
                af[mf][1] = As[cur][rb + 8][kb + tig];
                af[mf][2] = As[cur][rb    ][kb + tig + 4];
                af[mf][3] = As[cur][rb + 8][kb + tig + 4];
            }
#pragma unroll
            for (int nf = 0; nf < 8; nf++) {
                const int cb = wn * 64 + nf * 8 + gid;
                unsigned b0 = Bs[cur][kb + tig    ][cb];
                unsigned b1 = Bs[cur][kb + tig + 4][cb];
                mma_tf32(acc[0][nf], af[0][0], af[0][1], af[0][2], af[0][3], b0, b1);
                mma_tf32(acc[1][nf], af[1][0], af[1][1], af[1][2], af[1][3], b0, b1);
            }
        }

        if (kn < Dd) {
            const int nxt = cur ^ 1;
            uint4 u0 = { f2tf(ra0.x), f2tf(ra0.y), f2tf(ra0.z), f2tf(ra0.w) };
            uint4 u1 = { f2tf(ra1.x), f2tf(ra1.y), f2tf(ra1.z), f2tf(ra1.w) };
            *(uint4*)&As[nxt][arow     ][acg] = u0;
            *(uint4*)&As[nxt][arow + 64][acg] = u1;
            uint4 v0 = { f2tf(rb0.x), f2tf(rb0.y), f2tf(rb0.z), f2tf(rb0.w) };
            uint4 v1 = { f2tf(rb1.x), f2tf(rb1.y), f2tf(rb1.z), f2tf(rb1.w) };
            *(uint4*)&Bs[nxt][brow    ][bcn] = v0;
            *(uint4*)&Bs[nxt][brow + 8][bcn] = v1;
            __syncthreads();
            cur = nxt;
        }
    }

    const int which = bn / Dd;
    const int hbase = (bn % Dd) / HD;
    float* dst = (which == 0) ? g_q : ((which == 1) ? g_k : g_v);
#pragma unroll
    for (int mf = 0; mf < 2; mf++) {
#pragma unroll
        for (int nf = 0; nf < 8; nf++) {
            const int ncol = wn * 64 + nf * 8 + 2 * tig;
            const int h = hbase + (ncol >> 6);
            const int dd = ncol & 63;
            const float bi0 = bias[bn + ncol], bi1 = bias[bn + ncol + 1];
#pragma unroll
            for (int rr = 0; rr < 2; rr++) {
                const int m = bm + wm * 32 + mf * 16 + gid + rr * 8;
                const int b = m / Ss, s = m % Ss;
                float* drow = dst + ((size_t)(b * Hh + h) * Ss + s) * HD;
                drow[dd]     = acc[mf][nf][rr * 2]     + bi0;
                drow[dd + 1] = acc[mf][nf][rr * 2 + 1] + bi1;
            }
        }
    }
}

// ---------------------------------------------------------------------------
// Kernel 2: causal flash attention, tf32 mma, v2.
// 128 threads / 4 warps; block = 128 q-rows, warp = 32 q-rows; k-tiles of 32.
// Q fragments live in REGISTERS (loaded once) -> no A-side LDS in S-matmul.
// smem: Q staging buffer aliases the Ks/Vs/Ps region (union via raw array).
// ---------------------------------------------------------------------------
#define SM_KS 0
#define SM_VS (32*68*4)                    /* 8704  */
#define SM_PS (SM_VS + 32*72*4)            /* 17920 */
#define SM_TOT (SM_PS + 128*36*4)          /* 36352 */

__global__ void __launch_bounds__(128, 2) attn_mma()
{
    __shared__ __align__(16) unsigned char smraw[SM_TOT];
    typedef unsigned (*arr68)[68];
    typedef unsigned (*arr72)[72];
    typedef unsigned (*arr36)[36];
    arr68 Qstage = (arr68)smraw;           // [128][68], transient (aliases below)
    arr68 Ks = (arr68)(smraw + SM_KS);     // [32][68]
    arr72 Vs = (arr72)(smraw + SM_VS);     // [32][72]
    arr36 Ps = (arr36)(smraw + SM_PS);     // [128][36]

    const int bh = blockIdx.y;
    const int qt = gridDim.x - 1 - (int)blockIdx.x;   // heaviest blocks first
    const int q0 = qt * 128;
    const int tid = threadIdx.x;
    const int warp = tid >> 5, lane = tid & 31;
    const int gid = lane >> 2, tig = lane & 3;
    const int w32 = warp * 32;

    // ---- stage Q (scaled) once, pull fragments into registers ----
    const float* Qg = g_q + ((size_t)bh * Ss + q0) * HD;
#pragma unroll
    for (int i = 0; i < 16; i++) {
        const int idx = tid + i * 128;                // 2048 float4
        const int r = idx >> 4, c = (idx & 15) * 4;
        float4 a = *(const float4*)(Qg + r * HD + c);
        uint4 u = { f2tf(a.x * 0.125f), f2tf(a.y * 0.125f),
                    f2tf(a.z * 0.125f), f2tf(a.w * 0.125f) };
        *(uint4*)&Qstage[r][c] = u;
    }
    __syncthreads();

    unsigned qf[8][2][4];                              // 64 regs, loop-invariant
#pragma unroll
    for (int kk = 0; kk < 8; kk++) {
        const int kb = kk * 8;
#pragma unroll
        for (int mf = 0; mf < 2; mf++) {
            const int rb = w32 + mf * 16 + gid;
            qf[kk][mf][0] = Qstage[rb    ][kb + tig];
            qf[kk][mf][1] = Qstage[rb + 8][kb + tig];
            qf[kk][mf][2] = Qstage[rb    ][kb + tig + 4];
            qf[kk][mf][3] = Qstage[rb + 8][kb + tig + 4];
        }
    }
    __syncthreads();   // all Q reads done before Ks/Vs overwrite the buffer

    float o[2][8][4] = {};
    float m[2][2] = { {-1e30f,-1e30f}, {-1e30f,-1e30f} };
    float l[2][2] = { {0.f,0.f}, {0.f,0.f} };

    const int nkt = (q0 + 128) / 32;

    // prologue: tile 0 into regs (512 float4 each: 4/thread)
    float4 rk[4], rv[4];
#pragma unroll
    for (int i = 0; i < 4; i++) {
        const int idx = tid + i * 128;
        const int r = idx >> 4, c = (idx & 15) * 4;
        rk[i] = *(const float4*)(g_k + ((size_t)bh * Ss + r) * HD + c);
        rv[i] = *(const float4*)(g_v + ((size_t)bh * Ss + r) * HD + c);
    }

    for (int kt = 0; kt < nkt; kt++) {
        const int k0 = kt * 32;
        __syncthreads();
#pragma unroll
        for (int i = 0; i < 4; i++) {
            const int idx = tid + i * 128;
            const int r = idx >> 4, c = (idx & 15) * 4;
            uint4 u = { f2tf(rk[i].x), f2tf(rk[i].y), f2tf(rk[i].z), f2tf(rk[i].w) };
            *(uint4*)&Ks[r][c] = u;
            uint4 v = { f2tf(rv[i].x), f2tf(rv[i].y), f2tf(rv[i].z), f2tf(rv[i].w) };
            *(uint4*)&Vs[r][c] = v;
        }
        __syncthreads();

        if (kt + 1 < nkt) {
            const int kn0 = k0 + 32;
#pragma unroll
            for (int i = 0; i < 4; i++) {
                const int idx = tid + i * 128;
                const int r = idx >> 4, c = (idx & 15) * 4;
                rk[i] = *(const float4*)(g_k + ((size_t)bh * Ss + kn0 + r) * HD + c);
                rv[i] = *(const float4*)(g_v + ((size_t)bh * Ss + kn0 + r) * HD + c);
            }
        }

        if (k0 <= q0 + w32 + 31) {                     // warp participates
            float s[2][4][4] = {};
#pragma unroll
            for (int kk = 0; kk < 8; kk++) {
                const int kb = kk * 8;
#pragma unroll
                for (int nf = 0; nf < 4; nf++) {
                    const int cb = nf * 8 + gid;
                    unsigned b0 = Ks[cb][kb + tig];
                    unsigned b1 = Ks[cb][kb + tig + 4];
                    mma_tf32(s[0][nf], qf[kk][0][0], qf[kk][0][1],
                                       qf[kk][0][2], qf[kk][0][3], b0, b1);
                    mma_tf32(s[1][nf], qf[kk][1][0], qf[kk][1][1],
                                       qf[kk][1][2], qf[kk][1][3], b0, b1);
                }
            }

            if (k0 + 32 > q0 + w32) {                  // diagonal overlap: mask
#pragma unroll
                for (int mf = 0; mf < 2; mf++) {
                    const int r0 = q0 + w32 + mf * 16 + gid, r1 = r0 + 8;
#pragma unroll
                    for (int nf = 0; nf < 4; nf++) {
                        const int cg = k0 + nf * 8 + 2 * tig;
                        if (cg     > r0) s[mf][nf][0] = -1e30f;
                        if (cg + 1 > r0) s[mf][nf][1] = -1e30f;
                        if (cg     > r1) s[mf][nf][2] = -1e30f;
                        if (cg + 1 > r1) s[mf][nf][3] = -1e30f;
                    }
                }
            }

#pragma unroll
            for (int mf = 0; mf < 2; mf++) {
                float t0 = -1e30f, t1 = -1e30f;
#pragma unroll
                for (int nf = 0; nf < 4; nf++) {
                    t0 = fmaxf(t0, fmaxf(s[mf][nf][0], s[mf][nf][1]));
                    t1 = fmaxf(t1, fmaxf(s[mf][nf][2], s[mf][nf][3]));
                }
                t0 = fmaxf(t0, __shfl_xor_sync(~0u, t0, 1));
                t0 = fmaxf(t0, __shfl_xor_sync(~0u, t0, 2));
                t1 = fmaxf(t1, __shfl_xor_sync(~0u, t1, 1));
                t1 = fmaxf(t1, __shfl_xor_sync(~0u, t1, 2));

                const float nm0 = fmaxf(m[mf][0], t0), nm1 = fmaxf(m[mf][1], t1);
                const float cr0 = __expf(m[mf][0] - nm0), cr1 = __expf(m[mf][1] - nm1);
                l[mf][0] *= cr0; l[mf][1] *= cr1;
#pragma unroll
                for (int nf = 0; nf < 8; nf++) {
                    o[mf][nf][0] *= cr0; o[mf][nf][1] *= cr0;
                    o[mf][nf][2] *= cr1; o[mf][nf][3] *= cr1;
                }
                m[mf][0] = nm0; m[mf][1] = nm1;

                float ls0 = 0.f, ls1 = 0.f;
#pragma unroll
                for (int nf = 0; nf < 4; nf++) {
                    const float p0 = __expf(s[mf][nf][0] - nm0);
                    const float p1 = __expf(s[mf][nf][1] - nm0);
                    const float p2 = __expf(s[mf][nf][2] - nm1);
                    const float p3 = __expf(s[mf][nf][3] - nm1);
                    ls0 += p0 + p1; ls1 += p2 + p3;
                    uint2 w01 = { f2tf(p0), f2tf(p1) };
                    uint2 w23 = { f2tf(p2), f2tf(p3) };
                    const int rb = w32 + mf * 16 + gid;
                    *(uint2*)&Ps[rb    ][nf * 8 + 2 * tig] = w01;
                    *(uint2*)&Ps[rb + 8][nf * 8 + 2 * tig] = w23;
                }
                ls0 += __shfl_xor_sync(~0u, ls0, 1);
                ls0 += __shfl_xor_sync(~0u, ls0, 2);
                ls1 += __shfl_xor_sync(~0u, ls1, 1);
                ls1 += __shfl_xor_sync(~0u, ls1, 2);
                l[mf][0] += ls0; l[mf][1] += ls1;
            }

            __syncwarp();                              // P visible within warp
#pragma unroll
            for (int kk = 0; kk < 4; kk++) {
                const int kb = kk * 8;
                unsigned af[2][4];
#pragma unroll
                for (int mf = 0; mf < 2; mf++) {
                    const int rb = w32 + mf * 16 + gid;
                    af[mf][0] = Ps[rb    ][kb + tig];
                    af[mf][1] = Ps[rb + 8][kb + tig];
                    af[mf][2] = Ps[rb    ][kb + tig + 4];
                    af[mf][3] = Ps[rb + 8][kb + tig + 4];
                }
#pragma unroll
                for (int nf = 0; nf < 8; nf++) {
                    const int cb = nf * 8 + gid;
                    unsigned b0 = Vs[kb + tig    ][cb];
                    unsigned b1 = Vs[kb + tig + 4][cb];
                    mma_tf32(o[0][nf], af[0][0], af[0][1], af[0][2], af[0][3], b0, b1);
                    mma_tf32(o[1][nf], af[1][0], af[1][1], af[1][2], af[1][3], b0, b1);
                }
            }
        }
    }

#pragma unroll
    for (int mf = 0; mf < 2; mf++) {
        const float inv0 = 1.f / l[mf][0], inv1 = 1.f / l[mf][1];
        float* O0 = g_ao + ((size_t)bh * Ss + q0 + w32 + mf * 16 + gid) * HD;
        float* O1 = O0 + 8 * HD;
#pragma unroll
        for (int nf = 0; nf < 8; nf++) {
            const int cg = nf * 8 + 2 * tig;
            O0[cg]     = o[mf][nf][0] * inv0;
            O0[cg + 1] = o[mf][nf][1] * inv0;
            O1[cg]     = o[mf][nf][2] * inv1;
            O1[cg + 1] = o[mf][nf][3] * inv1;
        }
    }
}

// ---------------------------------------------------------------------------
// Kernel 3: output projection, double-buffered (unchanged from R7).
// ---------------------------------------------------------------------------
__global__ void __launch_bounds__(256, 2) proj_gemm(const float* __restrict__ Wp,
                                                    const float* __restrict__ bias,
                                                    float* __restrict__ out)
{
    __shared__ unsigned As[2][128][20];
    __shared__ unsigned Bs[2][16][136];

    const int tid  = threadIdx.x;
    const int warp = tid >> 5, lane = tid & 31;
    const int wm = warp & 3, wn = warp >> 2;
    const int gid = lane >> 2, tig = lane & 3;
    const int bm = blockIdx.y * 128, bn = blockIdx.x * 128;

    const int arow = tid >> 2, acg = (tid & 3) * 4;
    const int brow = tid >> 5, bcn = (tid & 31) * 4;

    const int m0r = bm + arow;
    const int b0i = m0r / Ss, s0i = m0r % Ss;
    const int m1r = bm + arow + 64;
    const int b1i = m1r / Ss, s1i = m1r % Ss;

    float acc[2][8][4] = {};
    float4 ra0, ra1, rb0, rb1;

    {
        const int h = acg / HD, dd = acg % HD;
        ra0 = *(const float4*)(g_ao + ((size_t)(b0i * Hh + h) * Ss + s0i) * HD + dd);
        ra1 = *(const float4*)(g_ao + ((size_t)(b1i * Hh + h) * Ss + s1i) * HD + dd);
    }
    rb0 = *(const float4*)(Wp + (size_t)(brow)     * Dd + bn + bcn);
    rb1 = *(const float4*)(Wp + (size_t)(brow + 8) * Dd + bn + bcn);
    {
        uint4 u0 = { f2tf(ra0.x), f2tf(ra0.y), f2tf(ra0.z), f2tf(ra0.w) };
        uint4 u1 = { f2tf(ra1.x), f2tf(ra1.y), f2tf(ra1.z), f2tf(ra1.w) };
        *(uint4*)&As[0][arow     ][acg] = u0;
        *(uint4*)&As[0][arow + 64][acg] = u1;
        uint4 v0 = { f2tf(rb0.x), f2tf(rb0.y), f2tf(rb0.z), f2tf(rb0.w) };
        uint4 v1 = { f2tf(rb1.x), f2tf(rb1.y), f2tf(rb1.z), f2tf(rb1.w) };
        *(uint4*)&Bs[0][brow    ][bcn] = v0;
        *(uint4*)&Bs[0][brow + 8][bcn] = v1;
    }
    __syncthreads();

    int cur = 0;
    for (int k0 = 0; k0 < Dd; k0 += 16) {
        const int kn = k0 + 16;
        if (kn < Dd) {
            const int k = kn + acg;
            const int h = k / HD, dd = k % HD;
            ra0 = *(const float4*)(g_ao + ((size_t)(b0i * Hh + h) * Ss + s0i) * HD + dd);
            ra1 = *(const float4*)(g_ao + ((size_t)(b1i * Hh + h) * Ss + s1i) * HD + dd);
            rb0 = *(const float4*)(Wp + (size_t)(kn + brow)     * Dd + bn + bcn);
            rb1 = *(const float4*)(Wp + (size_t)(kn + brow + 8) * Dd + bn + bcn);
        }

#pragma unroll
        for (int ks = 0; ks < 2; ks++) {
            const int kb = ks * 8;
            unsigned af[2][4];
#pragma unroll
            for (int mf = 0; mf < 2; mf++) {
                const int rb = wm * 32 + mf * 16 + gid;
                af[mf][0] = As[cur][rb    ][kb + tig];
                af[mf][1] = As[cur][rb + 8][kb + tig];
                af[mf][2] = As[cur][rb    ][kb + tig + 4];
                af[mf][3] = As[cur][rb + 8][kb + tig + 4];
            }
#pragma unroll
            for (int nf = 0; nf < 8; nf++) {
                const int cb = wn * 64 + nf * 8 + gid;
                unsigned b0 = Bs[cur][kb + tig    ][cb];
                unsigned b1 = Bs[cur][kb + tig + 4][cb];
                mma_tf32(acc[0][nf], af[0][0], af[0][1], af[0][2], af[0][3], b0, b1);
                mma_tf32(acc[1][nf], af[1][0], af[1][1], af[1][2], af[1][3], b0, b1);
            }
        }

        if (kn < Dd) {
            const int nxt = cur ^ 1;
            uint4 u0 = { f2tf(ra0.x), f2tf(ra0.y), f2tf(ra0.z), f2tf(ra0.w) };
            uint4 u1 = { f2tf(ra1.x), f2tf(ra1.y), f2tf(ra1.z), f2tf(ra1.w) };
            *(uint4*)&As[nxt][arow     ][acg] = u0;
            *(uint4*)&As[nxt][arow + 64][acg] = u1;
            uint4 v0 = { f2tf(rb0.x), f2tf(rb0.y), f2tf(rb0.z), f2tf(rb0.w) };
            uint4 v1 = { f2tf(rb1.x), f2tf(rb1.y), f2tf(rb1.z), f2tf(rb1.w) };
            *(uint4*)&Bs[nxt][brow    ][bcn] = v0;
            *(uint4*)&Bs[nxt][brow + 8][bcn] = v1;
            __syncthreads();
            cur = nxt;
        }
    }

#pragma unroll
    for (int mf = 0; mf < 2; mf++) {
#pragma unroll
        for (int nf = 0; nf < 8; nf++) {
            const int ncol = wn * 64 + nf * 8 + 2 * tig;
            const float bi0 = bias[bn + ncol], bi1 = bias[bn + ncol + 1];
#pragma unroll
            for (int rr = 0; rr < 2; rr++) {
                const int m = bm + wm * 32 + mf * 16 + gid + rr * 8;
                out[(size_t)m * Dd + bn + ncol]     = acc[mf][nf][rr * 2]     + bi0;
                out[(size_t)m * Dd + bn + ncol + 1] = acc[mf][nf][rr * 2 + 1] + bi1;
            }
        }
    }
}

// ---------------------------------------------------------------------------
extern "C" void kernel_launch(void* const* d_in, const int* in_sizes, int n_in,
                              void* d_out, int out_size)
{
    const float* hs  = (const float*)d_in[0];   // hidden_states [B,S,D]
    const float* caw = (const float*)d_in[1];   // c_attn_w [D,3D]
    const float* cab = (const float*)d_in[2];   // c_attn_b [3D]
    const float* cpw = (const float*)d_in[3];   // c_proj_w [D,D]
    const float* cpb = (const float*)d_in[4];   // c_proj_b [D]
    float* out = (float*)d_out;                 // [B,S,D] fp32

    qkv_gemm<<<dim3(N3 / 128, Mm / 128), 256>>>(hs, caw, cab);
    attn_mma<<<dim3(Ss / 128, Bb * Hh), 128>>>();
    proj_gemm<<<dim3(Dd / 128, Mm / 128), 256>>>(cpw, cpb, out);
}